// round 1
// baseline (speedup 1.0000x reference)
#include <cuda_runtime.h>
#include <math.h>

#define N_ATOMS 65536
#define N_BONDS 98304
#define N_MOLS  4096
#define D_IN    128
#define D       256

// ---------------- scratch (device globals; no allocation allowed) ----------------
__device__ float g_he_a[(size_t)N_BONDS * D];
__device__ float g_he_b[(size_t)N_BONDS * D];
__device__ float g_he0 [(size_t)N_BONDS * D];
__device__ float g_hv_a[(size_t)N_ATOMS * D];
__device__ float g_hv_b[(size_t)N_ATOMS * D];
__device__ float g_hv0 [(size_t)N_ATOMS * D];
__device__ float g_ebv [(size_t)N_ATOMS * D];
__device__ float g_hu_a[(size_t)N_MOLS * D];
__device__ float g_hu_b[(size_t)N_MOLS * D];
__device__ float g_hu0 [(size_t)N_MOLS * D];
__device__ float g_ebar[(size_t)N_MOLS * D];
__device__ float g_vbar[(size_t)N_MOLS * D];
__device__ float g_mmean[(size_t)N_MOLS * D_IN];
__device__ int   g_boff[N_MOLS + 1];
__device__ int   g_aoff[N_MOLS + 1];

// ---------------- packed f32x2 helpers ----------------
__device__ __forceinline__ void ffma2(unsigned long long &d,
                                      unsigned long long a,
                                      unsigned long long b) {
    asm("fma.rn.f32x2 %0, %1, %2, %0;" : "+l"(d) : "l"(a), "l"(b));
}
__device__ __forceinline__ unsigned long long bcast2(float x) {
    unsigned int xi = __float_as_uint(x);
    unsigned long long r;
    asm("mov.b64 %0, {%1, %1};" : "=l"(r) : "r"(xi));
    return r;
}
__device__ __forceinline__ float lo32(unsigned long long v) {
    return __uint_as_float((unsigned int)(v & 0xffffffffull));
}
__device__ __forceinline__ float hi32(unsigned long long v) {
    return __uint_as_float((unsigned int)(v >> 32));
}

// ---------------- fused multi-source GEMM + tanh ----------------
// out[m, n] = tanh( sum_s  A_s[row_s(m), :ksrc] @ W[s*ksrc:(s+1)*ksrc, n] )
// row_s(m) = idx_s ? idx_s[m] : m.  W row-major [n_src*ksrc, 256].
struct Srcs {
    const float* A[5];
    const int*   idx[5];
};

#define BM   128
#define BN   64
#define BK   16
#define ASTR 136  // padded stride for conflict reduction

__global__ void __launch_bounds__(256, 2)
k_gemm_tanh(Srcs srcs, int n_src, int ksrc, int kshift,
            const float* __restrict__ W,
            float* __restrict__ out, float* __restrict__ out2)
{
    __shared__ float As[BK][ASTR];
    __shared__ float Bs[BK][BN];

    const int tid = threadIdx.x;
    const int m0  = blockIdx.y * BM;
    const int n0  = blockIdx.x * BN;

    const int tx = tid & 15;   // n: tx*4 .. +3
    const int ty = tid >> 4;   // m: ty*8 .. +7

    const int a_row = tid >> 1;         // 0..127
    const int a_k   = (tid & 1) * 8;    // 0 or 8 (k offset, 8 floats per thread)
    const int b_row = tid >> 4;         // 0..15
    const int b_col = (tid & 15) * 4;   // 0..60

    const int tiles_per_src = ksrc >> 4;
    const int n_tiles = n_src * tiles_per_src;
    const int kmask   = tiles_per_src - 1;

    float4 a0, a1, b0;
    int cur_src;
    const float* a_ptr;
    const float* w_ptr = W + (size_t)b_row * D + n0 + b_col;

    // prefetch tile 0
    {
        cur_src = 0;
        int gr = m0 + a_row;
        if (srcs.idx[0]) gr = __ldg(srcs.idx[0] + gr);
        a_ptr = srcs.A[0] + (size_t)gr * ksrc + a_k;
        a0 = *(const float4*)(a_ptr);
        a1 = *(const float4*)(a_ptr + 4);
        b0 = *(const float4*)(w_ptr);
    }

    unsigned long long acc[4][4];
#pragma unroll
    for (int i = 0; i < 4; i++)
#pragma unroll
        for (int j = 0; j < 4; j++) acc[i][j] = 0ull;

    for (int t = 0; t < n_tiles; t++) {
        __syncthreads();
        As[a_k + 0][a_row] = a0.x;
        As[a_k + 1][a_row] = a0.y;
        As[a_k + 2][a_row] = a0.z;
        As[a_k + 3][a_row] = a0.w;
        As[a_k + 4][a_row] = a1.x;
        As[a_k + 5][a_row] = a1.y;
        As[a_k + 6][a_row] = a1.z;
        As[a_k + 7][a_row] = a1.w;
        *(float4*)&Bs[b_row][b_col] = b0;
        __syncthreads();

        if (t + 1 < n_tiles) {
            const int tn = t + 1;
            const int s  = tn >> kshift;
            if (s != cur_src) {
                cur_src = s;
                int gr = m0 + a_row;
                const int* idx = srcs.idx[s];
                if (idx) gr = __ldg(idx + gr);
                a_ptr = srcs.A[s] + (size_t)gr * ksrc + a_k;
            }
            const int kin = (tn & kmask) << 4;
            a0 = *(const float4*)(a_ptr + kin);
            a1 = *(const float4*)(a_ptr + kin + 4);
            b0 = *(const float4*)(w_ptr + (size_t)tn * BK * D);
        }

#pragma unroll
        for (int k = 0; k < BK; k++) {
            const ulonglong2 ap0 = *(const ulonglong2*)&As[k][ty * 8];
            const ulonglong2 ap1 = *(const ulonglong2*)&As[k][ty * 8 + 4];
            const float4 bv = *(const float4*)&Bs[k][tx * 4];
            const unsigned long long bp0 = bcast2(bv.x);
            const unsigned long long bp1 = bcast2(bv.y);
            const unsigned long long bp2 = bcast2(bv.z);
            const unsigned long long bp3 = bcast2(bv.w);
            ffma2(acc[0][0], ap0.x, bp0); ffma2(acc[0][1], ap0.x, bp1);
            ffma2(acc[0][2], ap0.x, bp2); ffma2(acc[0][3], ap0.x, bp3);
            ffma2(acc[1][0], ap0.y, bp0); ffma2(acc[1][1], ap0.y, bp1);
            ffma2(acc[1][2], ap0.y, bp2); ffma2(acc[1][3], ap0.y, bp3);
            ffma2(acc[2][0], ap1.x, bp0); ffma2(acc[2][1], ap1.x, bp1);
            ffma2(acc[2][2], ap1.x, bp2); ffma2(acc[2][3], ap1.x, bp3);
            ffma2(acc[3][0], ap1.y, bp0); ffma2(acc[3][1], ap1.y, bp1);
            ffma2(acc[3][2], ap1.y, bp2); ffma2(acc[3][3], ap1.y, bp3);
        }
    }

    // epilogue: tanh + store (each acc pair covers rows 2i, 2i+1)
#pragma unroll
    for (int i = 0; i < 4; i++) {
        const int r0 = m0 + ty * 8 + 2 * i;
        float4 c0, c1;
        c0.x = tanhf(lo32(acc[i][0])); c1.x = tanhf(hi32(acc[i][0]));
        c0.y = tanhf(lo32(acc[i][1])); c1.y = tanhf(hi32(acc[i][1]));
        c0.z = tanhf(lo32(acc[i][2])); c1.z = tanhf(hi32(acc[i][2]));
        c0.w = tanhf(lo32(acc[i][3])); c1.w = tanhf(hi32(acc[i][3]));
        const size_t o0 = (size_t)r0 * D + n0 + tx * 4;
        *(float4*)(out + o0)     = c0;
        *(float4*)(out + o0 + D) = c1;
        if (out2) {
            *(float4*)(out2 + o0)     = c0;
            *(float4*)(out2 + o0 + D) = c1;
        }
    }
}

// ---------------- small kernels ----------------
// segment start offsets via binary search (ids are sorted)
__global__ void k_offsets(const int* __restrict__ ids, int n, int* __restrict__ off)
{
    int m = blockIdx.x * blockDim.x + threadIdx.x;
    if (m > N_MOLS) return;
    int lo = 0, hi = n;
    while (lo < hi) {
        int mid = (lo + hi) >> 1;
        if (ids[mid] < m) lo = mid + 1; else hi = mid;
    }
    off[m] = lo;
}

// per-molecule mean of raw atom features (128 cols)
__global__ void k_mol_mean(const float* __restrict__ atoms,
                           const int* __restrict__ aoff,
                           float* __restrict__ mm)
{
    const int m = blockIdx.x, d = threadIdx.x;
    const int s = aoff[m], e = aoff[m + 1];
    float acc = 0.f;
    for (int i = s; i < e; i++) acc += atoms[(size_t)i * D_IN + d];
    float cnt = (float)(e - s);
    if (cnt < 1.f) cnt = 1.f;
    mm[(size_t)m * D_IN + d] = acc / cnt;
}

// h_e0[b,d] = tanh(bond_orders[b] * W_fe[d]); also seeds h_e
__global__ void k_init_he0(const float* __restrict__ bo,
                           const float* __restrict__ Wfe,
                           float* __restrict__ he0, float* __restrict__ he)
{
    const int b = blockIdx.x, d = threadIdx.x;
    const float v = tanhf(bo[b] * Wfe[d]);
    const size_t o = (size_t)b * D + d;
    he0[o] = v;
    he[o]  = v;
}

// scatter-add h_e into both endpoints
__global__ void k_scatter(const float* __restrict__ he,
                          const int* __restrict__ bsrc,
                          const int* __restrict__ bdst,
                          float* __restrict__ ebv)
{
    const int b = blockIdx.x, d = threadIdx.x;
    const float v = he[(size_t)b * D + d];
    const int s = __ldg(bsrc + b);
    const int t = __ldg(bdst + b);
    atomicAdd(ebv + (size_t)s * D + d, v);
    atomicAdd(ebv + (size_t)t * D + d, v);
}

// per-molecule segment sum over D=256 cols (sorted ids -> contiguous ranges)
__global__ void k_segsum(const float* __restrict__ x,
                         const int* __restrict__ off,
                         float* __restrict__ out)
{
    const int m = blockIdx.x, d = threadIdx.x;
    const int s = off[m], e = off[m + 1];
    float acc = 0.f;
    for (int i = s; i < e; i++) acc += x[(size_t)i * D + d];
    out[(size_t)m * D + d] = acc;
}

// ---------------- host orchestration (graph-capturable) ----------------
extern "C" void kernel_launch(void* const* d_in, const int* in_sizes, int n_in,
                              void* d_out, int out_size)
{
    const float* atoms       = (const float*)d_in[0];
    const float* bond_orders = (const float*)d_in[1];
    const int*   bond_src    = (const int*)  d_in[2];
    const int*   bond_dst    = (const int*)  d_in[3];
    const int*   atom_mol    = (const int*)  d_in[4];
    const int*   bond_mol    = (const int*)  d_in[5];
    const float* W_fe        = (const float*)d_in[6];
    const float* W_fv        = (const float*)d_in[7];
    const float* W_fu        = (const float*)d_in[8];
    const float* W_e         = (const float*)d_in[9];
    const float* W_v         = (const float*)d_in[10];
    const float* W_u         = (const float*)d_in[11];

    float *he_a, *he_b, *he0, *hv_a, *hv_b, *hv0, *ebv;
    float *hu_a, *hu_b, *hu0, *ebar, *vbar, *mmean;
    int *boff, *aoff;
    cudaGetSymbolAddress((void**)&he_a,  g_he_a);
    cudaGetSymbolAddress((void**)&he_b,  g_he_b);
    cudaGetSymbolAddress((void**)&he0,   g_he0);
    cudaGetSymbolAddress((void**)&hv_a,  g_hv_a);
    cudaGetSymbolAddress((void**)&hv_b,  g_hv_b);
    cudaGetSymbolAddress((void**)&hv0,   g_hv0);
    cudaGetSymbolAddress((void**)&ebv,   g_ebv);
    cudaGetSymbolAddress((void**)&hu_a,  g_hu_a);
    cudaGetSymbolAddress((void**)&hu_b,  g_hu_b);
    cudaGetSymbolAddress((void**)&hu0,   g_hu0);
    cudaGetSymbolAddress((void**)&ebar,  g_ebar);
    cudaGetSymbolAddress((void**)&vbar,  g_vbar);
    cudaGetSymbolAddress((void**)&mmean, g_mmean);
    cudaGetSymbolAddress((void**)&boff,  g_boff);
    cudaGetSymbolAddress((void**)&aoff,  g_aoff);

    const int offBlocks = (N_MOLS + 1 + 255) / 256;
    k_offsets<<<offBlocks, 256>>>(bond_mol, N_BONDS, boff);
    k_offsets<<<offBlocks, 256>>>(atom_mol, N_ATOMS, aoff);

    k_init_he0<<<N_BONDS, 256>>>(bond_orders, W_fe, he0, he_a);
    k_mol_mean<<<N_MOLS, 128>>>(atoms, aoff, mmean);

    // h_v0 = tanh(atoms @ W_fv); seed h_v
    {
        Srcs s = {};
        s.A[0] = atoms;
        k_gemm_tanh<<<dim3(D / BN, N_ATOMS / BM), 256>>>(s, 1, 128, 3, W_fv, hv0, hv_a);
    }
    // h_u0 = tanh(mol_mean @ W_fu); seed h_u
    {
        Srcs s = {};
        s.A[0] = mmean;
        k_gemm_tanh<<<dim3(D / BN, N_MOLS / BM), 256>>>(s, 1, 128, 3, W_fu, hu0, hu_a);
    }

    float *he_cur = he_a, *he_nxt = he_b;
    float *hv_cur = hv_a, *hv_nxt = hv_b;
    float *hu_cur = hu_a, *hu_nxt = hu_b;

    for (int it = 0; it < 3; it++) {
        float* eout = (it == 2) ? (float*)d_out : he_nxt;
        {
            Srcs s = {};
            s.A[0] = he_cur;
            s.A[1] = he0;
            s.A[2] = hv_cur; s.idx[2] = bond_src;
            s.A[3] = hv_cur; s.idx[3] = bond_dst;
            s.A[4] = hu_cur; s.idx[4] = bond_mol;
            k_gemm_tanh<<<dim3(D / BN, N_BONDS / BM), 256>>>(s, 5, 256, 4, W_e, eout, nullptr);
        }
        if (it == 2) break;  // output is h_e; remaining updates don't affect it
        { float* t = he_cur; he_cur = eout; he_nxt = t; }

        cudaMemsetAsync(ebv, 0, (size_t)N_ATOMS * D * sizeof(float), 0);
        k_scatter<<<N_BONDS, 256>>>(he_cur, bond_src, bond_dst, ebv);

        {
            Srcs s = {};
            s.A[0] = hv_cur;
            s.A[1] = hv0;
            s.A[2] = ebv;
            s.A[3] = hu_cur; s.idx[3] = atom_mol;
            k_gemm_tanh<<<dim3(D / BN, N_ATOMS / BM), 256>>>(s, 4, 256, 4, W_v, hv_nxt, nullptr);
        }
        { float* t = hv_cur; hv_cur = hv_nxt; hv_nxt = t; }

        k_segsum<<<N_MOLS, 256>>>(he_cur, boff, ebar);
        k_segsum<<<N_MOLS, 256>>>(hv_cur, aoff, vbar);

        {
            Srcs s = {};
            s.A[0] = hu_cur;
            s.A[1] = hu0;
            s.A[2] = ebar;
            s.A[3] = vbar;
            k_gemm_tanh<<<dim3(D / BN, N_MOLS / BM), 256>>>(s, 4, 256, 4, W_u, hu_nxt, nullptr);
        }
        { float* t = hu_cur; hu_cur = hu_nxt; hu_nxt = t; }
    }
}

// round 4
// speedup vs baseline: 1.5265x; 1.5265x over previous
#include <cuda_runtime.h>
#include <cuda_bf16.h>
#include <math.h>
#include <stdint.h>

typedef __nv_bfloat16 bf16;

#define N_ATOMS 65536
#define N_BONDS 98304
#define N_MOLS  4096
#define D_IN    128
#define D       256

// ---------------- scratch (device globals; no allocation allowed) ----------------
// activations stored as bf16 hi/lo planes (hi + lo ~= fp32 value to 2^-18)
__device__ bf16 g_he_hi [2][(size_t)N_BONDS * D];
__device__ bf16 g_he_lo [2][(size_t)N_BONDS * D];
__device__ bf16 g_he0_hi[(size_t)N_BONDS * D];
__device__ bf16 g_he0_lo[(size_t)N_BONDS * D];
__device__ bf16 g_hv_hi [2][(size_t)N_ATOMS * D];
__device__ bf16 g_hv_lo [2][(size_t)N_ATOMS * D];
__device__ bf16 g_hv0_hi[(size_t)N_ATOMS * D];
__device__ bf16 g_hv0_lo[(size_t)N_ATOMS * D];
__device__ float g_ebv_f [(size_t)N_ATOMS * D];
__device__ bf16 g_ebv_hi[(size_t)N_ATOMS * D];
__device__ bf16 g_ebv_lo[(size_t)N_ATOMS * D];
__device__ bf16 g_hu_hi [2][(size_t)N_MOLS * D];
__device__ bf16 g_hu_lo [2][(size_t)N_MOLS * D];
__device__ bf16 g_hu0_hi[(size_t)N_MOLS * D];
__device__ bf16 g_hu0_lo[(size_t)N_MOLS * D];
__device__ bf16 g_ebar_hi[(size_t)N_MOLS * D];
__device__ bf16 g_ebar_lo[(size_t)N_MOLS * D];
__device__ bf16 g_vbar_hi[(size_t)N_MOLS * D];
__device__ bf16 g_vbar_lo[(size_t)N_MOLS * D];
__device__ bf16 g_mm_hi [(size_t)N_MOLS * D_IN];
__device__ bf16 g_mm_lo [(size_t)N_MOLS * D_IN];
__device__ bf16 g_at_hi [(size_t)N_ATOMS * D_IN];
__device__ bf16 g_at_lo [(size_t)N_ATOMS * D_IN];
// weights transposed to [256 x K] (k contiguous), bf16 hi/lo planes
__device__ bf16 g_we_hi [(size_t)D * 5 * D];
__device__ bf16 g_we_lo [(size_t)D * 5 * D];
__device__ bf16 g_wv_hi [(size_t)D * 4 * D];
__device__ bf16 g_wv_lo [(size_t)D * 4 * D];
__device__ bf16 g_wu_hi [(size_t)D * 4 * D];
__device__ bf16 g_wu_lo [(size_t)D * 4 * D];
__device__ bf16 g_wfv_hi[(size_t)D * D_IN];
__device__ bf16 g_wfv_lo[(size_t)D * D_IN];
__device__ bf16 g_wfu_hi[(size_t)D * D_IN];
__device__ bf16 g_wfu_lo[(size_t)D * D_IN];
__device__ int  g_boff[N_MOLS + 1];
__device__ int  g_aoff[N_MOLS + 1];

// ---------------- helpers ----------------
__device__ __forceinline__ uint32_t smem_u32(const void* p) {
    uint32_t a;
    asm("{ .reg .u64 t; cvta.to.shared.u64 t, %1; cvt.u32.u64 %0, t; }" : "=r"(a) : "l"(p));
    return a;
}
__device__ __forceinline__ void cp16(uint32_t dst, const void* src) {
    asm volatile("cp.async.cg.shared.global [%0], [%1], 16;" :: "r"(dst), "l"(src) : "memory");
}
#define CP_COMMIT()  asm volatile("cp.async.commit_group;" ::: "memory")
#define CP_WAIT0()   asm volatile("cp.async.wait_group 0;" ::: "memory")

__device__ __forceinline__ void mma_bf16(float* c, const uint32_t* a, const uint32_t* b) {
    asm volatile(
        "mma.sync.aligned.m16n8k16.row.col.f32.bf16.bf16.f32 "
        "{%0,%1,%2,%3}, {%4,%5,%6,%7}, {%8,%9}, {%0,%1,%2,%3};"
        : "+f"(c[0]), "+f"(c[1]), "+f"(c[2]), "+f"(c[3])
        : "r"(a[0]), "r"(a[1]), "r"(a[2]), "r"(a[3]), "r"(b[0]), "r"(b[1]));
}
__device__ __forceinline__ void red4(float* p, float4 v) {
    asm volatile("red.global.add.v4.f32 [%0], {%1,%2,%3,%4};"
        :: "l"(p), "f"(v.x), "f"(v.y), "f"(v.z), "f"(v.w) : "memory");
}
__device__ __forceinline__ void split1(float v, bf16& h, bf16& l) {
    h = __float2bfloat16(v);
    l = __float2bfloat16(v - __bfloat162float(h));
}
__device__ __forceinline__ void split2(float v0, float v1, uint32_t& h2, uint32_t& l2) {
    bf16 h0, l0, h1, l1;
    split1(v0, h0, l0);
    split1(v1, h1, l1);
    h2 = (uint32_t)__bfloat16_as_ushort(h0) | ((uint32_t)__bfloat16_as_ushort(h1) << 16);
    l2 = (uint32_t)__bfloat16_as_ushort(l0) | ((uint32_t)__bfloat16_as_ushort(l1) << 16);
}

// ---------------- fused multi-source bf16x3 GEMM + tanh ----------------
// out[m, 0:256] = tanh( sum_s (Ahi+Alo)_s[row_s(m), :] @ (Whi+Wlo)[...] )
struct Srcs {
    const bf16* Ahi[5];
    const bf16* Alo[5];
    const int*  idx[5];
};

// smem: A planes [plane][buf][128][40 bf16] then B planes; 80B rows, stride 40 bf16
#define TILE_B   10240                   // one plane-buffer: 128*80
#define SM_A     0
#define SM_B     40960
#define SMEM_BYTES 81920

__global__ void __launch_bounds__(256)
k_mma(Srcs srcs, int ksrc, int cshift,
      const bf16* __restrict__ Whi, const bf16* __restrict__ Wlo, int Ktot,
      float* __restrict__ out_f32,
      bf16* __restrict__ out_hi, bf16* __restrict__ out_lo,
      bf16* __restrict__ out2_hi, bf16* __restrict__ out2_lo)
{
    extern __shared__ char smc[];
    const uint32_t smu = smem_u32(smc);

    const int tid  = threadIdx.x;
    const int lane = tid & 31;
    const int w    = tid >> 5;
    const int wm   = w & 3;      // 4 M-groups of 32 rows
    const int wn   = w >> 2;     // 2 N-groups of 64 cols
    const int lr   = lane >> 2;  // 0..7
    const int lc   = lane & 3;   // 0..3

    const int n0 = blockIdx.x * 128;
    const int m0 = blockIdx.y * 128;

    const int C     = Ktot >> 5;
    const int cmask = (ksrc >> 5) - 1;

    // producer: thread -> (row = tid>>1, plane = tid&1); 64B per row per plane
    const int arow = tid >> 1;
    const int apl  = tid & 1;
    int cur_s = -1;
    const bf16* aptr = srcs.Ahi[0];
    const bf16* wbase = apl ? Wlo : Whi;

    auto load_chunk = [&](int c) {
        const int buf = c & 1;
        const int s = c >> cshift;
        if (s != cur_s) {
            cur_s = s;
            int gr = m0 + arow;
            const int* ix = srcs.idx[s];
            if (ix) gr = __ldg(ix + gr);
            aptr = (apl ? srcs.Alo[s] : srcs.Ahi[s]) + (size_t)gr * ksrc;
        }
        const bf16* as = aptr + ((c & cmask) << 5);
        const uint32_t ad = smu + (uint32_t)(SM_A + apl * 2 * TILE_B + buf * TILE_B + arow * 80);
        cp16(ad,      as);
        cp16(ad + 16, as + 8);
        cp16(ad + 32, as + 16);
        cp16(ad + 48, as + 24);
        const bf16* bs = wbase + (size_t)(n0 + arow) * Ktot + ((size_t)c << 5);
        const uint32_t bd = smu + (uint32_t)(SM_B + apl * 2 * TILE_B + buf * TILE_B + arow * 80);
        cp16(bd,      bs);
        cp16(bd + 16, bs + 8);
        cp16(bd + 32, bs + 16);
        cp16(bd + 48, bs + 24);
    };

    float acc[2][8][4];
#pragma unroll
    for (int mi = 0; mi < 2; mi++)
#pragma unroll
        for (int nj = 0; nj < 8; nj++)
#pragma unroll
            for (int q = 0; q < 4; q++) acc[mi][nj][q] = 0.f;

    load_chunk(0);
    CP_COMMIT();

    for (int c = 0; c < C; c++) {
        CP_WAIT0();
        __syncthreads();
        if (c + 1 < C) load_chunk(c + 1);
        CP_COMMIT();

        const int buf = c & 1;
        const uint32_t* Ah = (const uint32_t*)(smc + SM_A + buf * TILE_B);
        const uint32_t* Al = (const uint32_t*)(smc + SM_A + 2 * TILE_B + buf * TILE_B);
        const uint32_t* Bh = (const uint32_t*)(smc + SM_B + buf * TILE_B);
        const uint32_t* Bl = (const uint32_t*)(smc + SM_B + 2 * TILE_B + buf * TILE_B);

#pragma unroll
        for (int kk2 = 0; kk2 < 16; kk2 += 8) {   // two k16 steps (uint32 units)
            uint32_t ah[2][4], al[2][4];
#pragma unroll
            for (int mi = 0; mi < 2; mi++) {
                const int o = (wm * 32 + mi * 16 + lr) * 20 + kk2 + lc;
                ah[mi][0] = Ah[o];       ah[mi][1] = Ah[o + 160];
                ah[mi][2] = Ah[o + 4];   ah[mi][3] = Ah[o + 164];
                al[mi][0] = Al[o];       al[mi][1] = Al[o + 160];
                al[mi][2] = Al[o + 4];   al[mi][3] = Al[o + 164];
            }
            uint32_t bh[8][2], bl[8][2];
#pragma unroll
            for (int nj = 0; nj < 8; nj++) {
                const int o = (wn * 64 + nj * 8 + lr) * 20 + kk2 + lc;
                bh[nj][0] = Bh[o]; bh[nj][1] = Bh[o + 4];
                bl[nj][0] = Bl[o]; bl[nj][1] = Bl[o + 4];
            }
#pragma unroll
            for (int mi = 0; mi < 2; mi++)
#pragma unroll
                for (int nj = 0; nj < 8; nj++) {
                    mma_bf16(acc[mi][nj], ah[mi], bh[nj]);
                    mma_bf16(acc[mi][nj], ah[mi], bl[nj]);
                    mma_bf16(acc[mi][nj], al[mi], bh[nj]);
                }
        }
        __syncthreads();
    }

    // epilogue
#pragma unroll
    for (int mi = 0; mi < 2; mi++) {
        const int r0 = m0 + wm * 32 + mi * 16 + lr;
#pragma unroll
        for (int nj = 0; nj < 8; nj++) {
            const int col = n0 + wn * 64 + nj * 8 + lc * 2;
            const float v0 = tanhf(acc[mi][nj][0]);
            const float v1 = tanhf(acc[mi][nj][1]);
            const float v2 = tanhf(acc[mi][nj][2]);
            const float v3 = tanhf(acc[mi][nj][3]);
            if (out_f32) {
                *(float2*)(out_f32 + (size_t)r0 * D + col)       = make_float2(v0, v1);
                *(float2*)(out_f32 + (size_t)(r0 + 8) * D + col) = make_float2(v2, v3);
            }
            if (out_hi) {
                uint32_t h01, l01, h23, l23;
                split2(v0, v1, h01, l01);
                split2(v2, v3, h23, l23);
                const size_t o0 = (size_t)r0 * D + col;
                const size_t o1 = (size_t)(r0 + 8) * D + col;
                *(uint32_t*)(out_hi + o0) = h01;  *(uint32_t*)(out_lo + o0) = l01;
                *(uint32_t*)(out_hi + o1) = h23;  *(uint32_t*)(out_lo + o1) = l23;
                if (out2_hi) {
                    *(uint32_t*)(out2_hi + o0) = h01;  *(uint32_t*)(out2_lo + o0) = l01;
                    *(uint32_t*)(out2_hi + o1) = h23;  *(uint32_t*)(out2_lo + o1) = l23;
                }
            }
        }
    }
}

// ---------------- small kernels ----------------
__global__ void k_offsets(const int* __restrict__ ids, int n, int* __restrict__ off)
{
    int m = blockIdx.x * blockDim.x + threadIdx.x;
    if (m > N_MOLS) return;
    int lo = 0, hi = n;
    while (lo < hi) {
        int mid = (lo + hi) >> 1;
        if (ids[mid] < m) lo = mid + 1; else hi = mid;
    }
    off[m] = lo;
}

__global__ void k_mol_mean(const float* __restrict__ atoms,
                           const int* __restrict__ aoff,
                           bf16* __restrict__ mhi, bf16* __restrict__ mlo)
{
    const int m = blockIdx.x, d = threadIdx.x;
    const int s = aoff[m], e = aoff[m + 1];
    float acc = 0.f;
    for (int i = s; i < e; i++) acc += atoms[(size_t)i * D_IN + d];
    float cnt = (float)(e - s);
    if (cnt < 1.f) cnt = 1.f;
    bf16 h, l;
    split1(acc / cnt, h, l);
    mhi[(size_t)m * D_IN + d] = h;
    mlo[(size_t)m * D_IN + d] = l;
}

// h_e0 = tanh(bond_orders ⊗ W_fe); seeds h_e. 2 cols/thread, packed stores.
__global__ void k_init_he0(const float* __restrict__ bo,
                           const float* __restrict__ Wfe,
                           bf16* __restrict__ e0hi, bf16* __restrict__ e0lo,
                           bf16* __restrict__ ehi,  bf16* __restrict__ elo)
{
    const int b = blockIdx.x, d = threadIdx.x * 2;
    const float o = bo[b];
    uint32_t h2, l2;
    split2(tanhf(o * Wfe[d]), tanhf(o * Wfe[d + 1]), h2, l2);
    const size_t off = (size_t)b * D + d;
    *(uint32_t*)(e0hi + off) = h2;  *(uint32_t*)(e0lo + off) = l2;
    *(uint32_t*)(ehi + off)  = h2;  *(uint32_t*)(elo + off)  = l2;
}

// scatter-add h_e (hi+lo reconstructed) into both endpoints via red.global.v4
__global__ void k_scatter(const bf16* __restrict__ hehi, const bf16* __restrict__ helo,
                          const int* __restrict__ bsrc, const int* __restrict__ bdst,
                          float* __restrict__ ebv)
{
    const int t = blockIdx.x * blockDim.x + threadIdx.x;
    const int b = t >> 6;
    const int c4 = (t & 63) << 2;
    const size_t off = (size_t)b * D + c4;
    const __nv_bfloat162* h2 = (const __nv_bfloat162*)(hehi + off);
    const __nv_bfloat162* l2 = (const __nv_bfloat162*)(helo + off);
    float2 a0 = __bfloat1622float2(h2[0]), b0 = __bfloat1622float2(l2[0]);
    float2 a1 = __bfloat1622float2(h2[1]), b1 = __bfloat1622float2(l2[1]);
    float4 v = make_float4(a0.x + b0.x, a0.y + b0.y, a1.x + b1.x, a1.y + b1.y);
    const int s = __ldg(bsrc + b);
    const int d = __ldg(bdst + b);
    red4(ebv + (size_t)s * D + c4, v);
    red4(ebv + (size_t)d * D + c4, v);
}

// per-molecule segment sum over D=256 cols; reads planes, writes planes
__global__ void k_segsum(const bf16* __restrict__ xhi, const bf16* __restrict__ xlo,
                         const int* __restrict__ off,
                         bf16* __restrict__ ohi, bf16* __restrict__ olo)
{
    const int m = blockIdx.x, d = threadIdx.x;
    const int s = off[m], e = off[m + 1];
    float acc = 0.f;
    for (int i = s; i < e; i++) {
        const size_t o = (size_t)i * D + d;
        acc += __bfloat162float(xhi[o]) + __bfloat162float(xlo[o]);
    }
    bf16 h, l;
    split1(acc, h, l);
    ohi[(size_t)m * D + d] = h;
    olo[(size_t)m * D + d] = l;
}

// fp32 -> bf16 hi/lo planes (2 elements per thread)
__global__ void k_f2p(const float* __restrict__ in,
                      bf16* __restrict__ hi, bf16* __restrict__ lo, int n2)
{
    int i = blockIdx.x * blockDim.x + threadIdx.x;
    if (i >= n2) return;
    float2 v = ((const float2*)in)[i];
    uint32_t h2, l2;
    split2(v.x, v.y, h2, l2);
    ((uint32_t*)hi)[i] = h2;
    ((uint32_t*)lo)[i] = l2;
}

// W [K x 256] fp32 -> transposed planes [256 x K] bf16 hi/lo
__global__ void k_transpose_planes(const float* __restrict__ W,
                                   bf16* __restrict__ Thi, bf16* __restrict__ Tlo, int K)
{
    __shared__ float t[32][33];
    const int k0 = blockIdx.x * 32, nb = blockIdx.y * 32;
    const int tx = threadIdx.x, ty = threadIdx.y;
#pragma unroll
    for (int i = 0; i < 4; i++)
        t[ty + 8 * i][tx] = W[(size_t)(k0 + ty + 8 * i) * D + nb + tx];
    __syncthreads();
#pragma unroll
    for (int i = 0; i < 4; i++) {
        bf16 h, l;
        split1(t[tx][ty + 8 * i], h, l);
        const size_t o = (size_t)(nb + ty + 8 * i) * K + k0 + tx;
        Thi[o] = h;
        Tlo[o] = l;
    }
}

// ---------------- host orchestration ----------------
static bf16* sym_bf16(const void* sym) {
    void* p = nullptr;
    cudaGetSymbolAddress(&p, sym);
    return (bf16*)p;
}

extern "C" void kernel_launch(void* const* d_in, const int* in_sizes, int n_in,
                              void* d_out, int out_size)
{
    const float* atoms       = (const float*)d_in[0];
    const float* bond_orders = (const float*)d_in[1];
    const int*   bond_src    = (const int*)  d_in[2];
    const int*   bond_dst    = (const int*)  d_in[3];
    const int*   atom_mol    = (const int*)  d_in[4];
    const int*   bond_mol    = (const int*)  d_in[5];
    const float* W_fe        = (const float*)d_in[6];
    const float* W_fv        = (const float*)d_in[7];
    const float* W_fu        = (const float*)d_in[8];
    const float* W_e         = (const float*)d_in[9];
    const float* W_v         = (const float*)d_in[10];
    const float* W_u         = (const float*)d_in[11];

    bf16* he_hi  = sym_bf16(g_he_hi);   bf16* he_lo  = sym_bf16(g_he_lo);
    bf16* he0_hi = sym_bf16(g_he0_hi);  bf16* he0_lo = sym_bf16(g_he0_lo);
    bf16* hv_hi  = sym_bf16(g_hv_hi);   bf16* hv_lo  = sym_bf16(g_hv_lo);
    bf16* hv0_hi = sym_bf16(g_hv0_hi);  bf16* hv0_lo = sym_bf16(g_hv0_lo);
    bf16* ebv_hi = sym_bf16(g_ebv_hi);  bf16* ebv_lo = sym_bf16(g_ebv_lo);
    bf16* hu_hi  = sym_bf16(g_hu_hi);   bf16* hu_lo  = sym_bf16(g_hu_lo);
    bf16* hu0_hi = sym_bf16(g_hu0_hi);  bf16* hu0_lo = sym_bf16(g_hu0_lo);
    bf16* ebar_hi= sym_bf16(g_ebar_hi); bf16* ebar_lo= sym_bf16(g_ebar_lo);
    bf16* vbar_hi= sym_bf16(g_vbar_hi); bf16* vbar_lo= sym_bf16(g_vbar_lo);
    bf16* mm_hi  = sym_bf16(g_mm_hi);   bf16* mm_lo  = sym_bf16(g_mm_lo);
    bf16* at_hi  = sym_bf16(g_at_hi);   bf16* at_lo  = sym_bf16(g_at_lo);
    bf16* we_hi  = sym_bf16(g_we_hi);   bf16* we_lo  = sym_bf16(g_we_lo);
    bf16* wv_hi  = sym_bf16(g_wv_hi);   bf16* wv_lo  = sym_bf16(g_wv_lo);
    bf16* wu_hi  = sym_bf16(g_wu_hi);   bf16* wu_lo  = sym_bf16(g_wu_lo);
    bf16* wfv_hi = sym_bf16(g_wfv_hi);  bf16* wfv_lo = sym_bf16(g_wfv_lo);
    bf16* wfu_hi = sym_bf16(g_wfu_hi);  bf16* wfu_lo = sym_bf16(g_wfu_lo);
    float* ebv_f = nullptr; { void* p; cudaGetSymbolAddress(&p, g_ebv_f); ebv_f = (float*)p; }
    int *boff, *aoff;
    { void* p; cudaGetSymbolAddress(&p, g_boff); boff = (int*)p; }
    { void* p; cudaGetSymbolAddress(&p, g_aoff); aoff = (int*)p; }

    const size_t SZ_E = (size_t)N_BONDS * D;
    const size_t SZ_V = (size_t)N_ATOMS * D;
    const size_t SZ_U = (size_t)N_MOLS * D;

    cudaFuncSetAttribute(k_mma, cudaFuncAttributeMaxDynamicSharedMemorySize, SMEM_BYTES);

    const int offBlocks = (N_MOLS + 1 + 255) / 256;
    k_offsets<<<offBlocks, 256>>>(bond_mol, N_BONDS, boff);
    k_offsets<<<offBlocks, 256>>>(atom_mol, N_ATOMS, aoff);

    // weights: transpose + split to bf16 planes
    k_transpose_planes<<<dim3(5 * D / 32, 8), dim3(32, 8)>>>(W_e,  we_hi,  we_lo,  5 * D);
    k_transpose_planes<<<dim3(4 * D / 32, 8), dim3(32, 8)>>>(W_v,  wv_hi,  wv_lo,  4 * D);
    k_transpose_planes<<<dim3(4 * D / 32, 8), dim3(32, 8)>>>(W_u,  wu_hi,  wu_lo,  4 * D);
    k_transpose_planes<<<dim3(D_IN / 32, 8),  dim3(32, 8)>>>(W_fv, wfv_hi, wfv_lo, D_IN);
    k_transpose_planes<<<dim3(D_IN / 32, 8),  dim3(32, 8)>>>(W_fu, wfu_hi, wfu_lo, D_IN);

    // raw atoms -> planes
    k_f2p<<<(int)((N_ATOMS * (size_t)D_IN / 2 + 255) / 256), 256>>>(atoms, at_hi, at_lo,
                                                                    N_ATOMS * D_IN / 2);
    k_init_he0<<<N_BONDS, 128>>>(bond_orders, W_fe, he0_hi, he0_lo, he_hi, he_lo);
    k_mol_mean<<<N_MOLS, 128>>>(atoms, aoff, mm_hi, mm_lo);

    // h_v0 = tanh(atoms @ W_fv); seed h_v
    {
        Srcs s = {};
        s.Ahi[0] = at_hi; s.Alo[0] = at_lo;
        k_mma<<<dim3(2, N_ATOMS / 128), 256, SMEM_BYTES>>>(
            s, D_IN, 2, wfv_hi, wfv_lo, D_IN,
            nullptr, hv0_hi, hv0_lo, hv_hi, hv_lo);
    }
    // h_u0 = tanh(mol_mean @ W_fu); seed h_u
    {
        Srcs s = {};
        s.Ahi[0] = mm_hi; s.Alo[0] = mm_lo;
        k_mma<<<dim3(2, N_MOLS / 128), 256, SMEM_BYTES>>>(
            s, D_IN, 2, wfu_hi, wfu_lo, D_IN,
            nullptr, hu0_hi, hu0_lo, hu_hi, hu_lo);
    }

    int ec = 0, vc = 0, uc = 0;   // ping-pong indices

    for (int it = 0; it < 3; it++) {
        // edge update
        {
            Srcs s = {};
            s.Ahi[0] = he_hi + (size_t)ec * SZ_E;  s.Alo[0] = he_lo + (size_t)ec * SZ_E;
            s.Ahi[1] = he0_hi;                      s.Alo[1] = he0_lo;
            s.Ahi[2] = hv_hi + (size_t)vc * SZ_V;  s.Alo[2] = hv_lo + (size_t)vc * SZ_V;
            s.idx[2] = bond_src;
            s.Ahi[3] = s.Ahi[2];                    s.Alo[3] = s.Alo[2];
            s.idx[3] = bond_dst;
            s.Ahi[4] = hu_hi + (size_t)uc * SZ_U;  s.Alo[4] = hu_lo + (size_t)uc * SZ_U;
            s.idx[4] = bond_mol;
            if (it == 2) {
                k_mma<<<dim3(2, N_BONDS / 128), 256, SMEM_BYTES>>>(
                    s, D, 3, we_hi, we_lo, 5 * D,
                    (float*)d_out, nullptr, nullptr, nullptr, nullptr);
                break;   // output is final h_e
            }
            const int en = ec ^ 1;
            k_mma<<<dim3(2, N_BONDS / 128), 256, SMEM_BYTES>>>(
                s, D, 3, we_hi, we_lo, 5 * D,
                nullptr, he_hi + (size_t)en * SZ_E, he_lo + (size_t)en * SZ_E,
                nullptr, nullptr);
            ec = en;
        }

        // e_bar_v scatter
        cudaMemsetAsync(ebv_f, 0, SZ_V * sizeof(float), 0);
        k_scatter<<<N_BONDS * 64 / 256, 256>>>(he_hi + (size_t)ec * SZ_E,
                                               he_lo + (size_t)ec * SZ_E,
                                               bond_src, bond_dst, ebv_f);
        k_f2p<<<(int)((SZ_V / 2 + 255) / 256), 256>>>(ebv_f, ebv_hi, ebv_lo, (int)(SZ_V / 2));

        // node update
        {
            Srcs s = {};
            s.Ahi[0] = hv_hi + (size_t)vc * SZ_V;  s.Alo[0] = hv_lo + (size_t)vc * SZ_V;
            s.Ahi[1] = hv0_hi;                      s.Alo[1] = hv0_lo;
            s.Ahi[2] = ebv_hi;                      s.Alo[2] = ebv_lo;
            s.Ahi[3] = hu_hi + (size_t)uc * SZ_U;  s.Alo[3] = hu_lo + (size_t)uc * SZ_U;
            s.idx[3] = atom_mol;
            const int vn = vc ^ 1;
            k_mma<<<dim3(2, N_ATOMS / 128), 256, SMEM_BYTES>>>(
                s, D, 3, wv_hi, wv_lo, 4 * D,
                nullptr, hv_hi + (size_t)vn * SZ_V, hv_lo + (size_t)vn * SZ_V,
                nullptr, nullptr);
            vc = vn;
        }

        // segment sums
        k_segsum<<<N_MOLS, 256>>>(he_hi + (size_t)ec * SZ_E, he_lo + (size_t)ec * SZ_E,
                                  boff, ebar_hi, ebar_lo);
        k_segsum<<<N_MOLS, 256>>>(hv_hi + (size_t)vc * SZ_V, hv_lo + (size_t)vc * SZ_V,
                                  aoff, vbar_hi, vbar_lo);

        // global update
        {
            Srcs s = {};
            s.Ahi[0] = hu_hi + (size_t)uc * SZ_U;  s.Alo[0] = hu_lo + (size_t)uc * SZ_U;
            s.Ahi[1] = hu0_hi;                      s.Alo[1] = hu0_lo;
            s.Ahi[2] = ebar_hi;                     s.Alo[2] = ebar_lo;
            s.Ahi[3] = vbar_hi;                     s.Alo[3] = vbar_lo;
            const int un = uc ^ 1;
            k_mma<<<dim3(2, N_MOLS / 128), 256, SMEM_BYTES>>>(
                s, D, 3, wu_hi, wu_lo, 4 * D,
                nullptr, hu_hi + (size_t)un * SZ_U, hu_lo + (size_t)un * SZ_U,
                nullptr, nullptr);
            uc = un;
        }
    }
}

// round 5
// speedup vs baseline: 1.6173x; 1.0595x over previous
#include <cuda_runtime.h>
#include <cuda_bf16.h>
#include <math.h>
#include <stdint.h>

typedef __nv_bfloat16 bf16;

#define N_ATOMS 65536
#define N_BONDS 98304
#define N_MOLS  4096
#define D_IN    128
#define D       256

// ---------------- scratch (device globals; no allocation allowed) ----------------
__device__ bf16 g_he_hi [2][(size_t)N_BONDS * D];
__device__ bf16 g_he_lo [2][(size_t)N_BONDS * D];
__device__ bf16 g_he0_hi[(size_t)N_BONDS * D];
__device__ bf16 g_he0_lo[(size_t)N_BONDS * D];
__device__ bf16 g_hv_hi [2][(size_t)N_ATOMS * D];
__device__ bf16 g_hv_lo [2][(size_t)N_ATOMS * D];
__device__ bf16 g_hv0_hi[(size_t)N_ATOMS * D];
__device__ bf16 g_hv0_lo[(size_t)N_ATOMS * D];
__device__ float g_ebv_f [(size_t)N_ATOMS * D];
__device__ bf16 g_ebv_hi[(size_t)N_ATOMS * D];
__device__ bf16 g_ebv_lo[(size_t)N_ATOMS * D];
__device__ bf16 g_hu_hi [2][(size_t)N_MOLS * D];
__device__ bf16 g_hu_lo [2][(size_t)N_MOLS * D];
__device__ bf16 g_hu0_hi[(size_t)N_MOLS * D];
__device__ bf16 g_hu0_lo[(size_t)N_MOLS * D];
__device__ bf16 g_ebar_hi[(size_t)N_MOLS * D];
__device__ bf16 g_ebar_lo[(size_t)N_MOLS * D];
__device__ bf16 g_vbar_hi[(size_t)N_MOLS * D];
__device__ bf16 g_vbar_lo[(size_t)N_MOLS * D];
__device__ bf16 g_mm_hi [(size_t)N_MOLS * D_IN];
__device__ bf16 g_mm_lo [(size_t)N_MOLS * D_IN];
__device__ bf16 g_at_hi [(size_t)N_ATOMS * D_IN];
__device__ bf16 g_at_lo [(size_t)N_ATOMS * D_IN];
__device__ bf16 g_we_hi [(size_t)D * 5 * D];
__device__ bf16 g_we_lo [(size_t)D * 5 * D];
__device__ bf16 g_wv_hi [(size_t)D * 4 * D];
__device__ bf16 g_wv_lo [(size_t)D * 4 * D];
__device__ bf16 g_wu_hi [(size_t)D * 4 * D];
__device__ bf16 g_wu_lo [(size_t)D * 4 * D];
__device__ bf16 g_wfv_hi[(size_t)D * D_IN];
__device__ bf16 g_wfv_lo[(size_t)D * D_IN];
__device__ bf16 g_wfu_hi[(size_t)D * D_IN];
__device__ bf16 g_wfu_lo[(size_t)D * D_IN];
__device__ int  g_boff[N_MOLS + 1];
__device__ int  g_aoff[N_MOLS + 1];

// ---------------- helpers ----------------
__device__ __forceinline__ uint32_t smem_u32(const void* p) {
    uint32_t a;
    asm("{ .reg .u64 t; cvta.to.shared.u64 t, %1; cvt.u32.u64 %0, t; }" : "=r"(a) : "l"(p));
    return a;
}
__device__ __forceinline__ void cp16(uint32_t dst, const void* src) {
    asm volatile("cp.async.cg.shared.global [%0], [%1], 16;" :: "r"(dst), "l"(src) : "memory");
}
#define CP_COMMIT()  asm volatile("cp.async.commit_group;" ::: "memory")
#define CP_WAIT0()   asm volatile("cp.async.wait_group 0;" ::: "memory")

__device__ __forceinline__ void ldsm4(uint32_t* r, uint32_t addr) {
    asm volatile("ldmatrix.sync.aligned.m8n8.x4.shared.b16 {%0,%1,%2,%3}, [%4];"
        : "=r"(r[0]), "=r"(r[1]), "=r"(r[2]), "=r"(r[3]) : "r"(addr));
}
__device__ __forceinline__ void mma_bf16(float* c, const uint32_t* a, const uint32_t* b) {
    asm volatile(
        "mma.sync.aligned.m16n8k16.row.col.f32.bf16.bf16.f32 "
        "{%0,%1,%2,%3}, {%4,%5,%6,%7}, {%8,%9}, {%0,%1,%2,%3};"
        : "+f"(c[0]), "+f"(c[1]), "+f"(c[2]), "+f"(c[3])
        : "r"(a[0]), "r"(a[1]), "r"(a[2]), "r"(a[3]), "r"(b[0]), "r"(b[1]));
}
__device__ __forceinline__ void red4(float* p, float4 v) {
    asm volatile("red.global.add.v4.f32 [%0], {%1,%2,%3,%4};"
        :: "l"(p), "f"(v.x), "f"(v.y), "f"(v.z), "f"(v.w) : "memory");
}
__device__ __forceinline__ void split1(float v, bf16& h, bf16& l) {
    h = __float2bfloat16(v);
    l = __float2bfloat16(v - __bfloat162float(h));
}
__device__ __forceinline__ void split2(float v0, float v1, uint32_t& h2, uint32_t& l2) {
    bf16 h0, l0, h1, l1;
    split1(v0, h0, l0);
    split1(v1, h1, l1);
    h2 = (uint32_t)__bfloat16_as_ushort(h0) | ((uint32_t)__bfloat16_as_ushort(h1) << 16);
    l2 = (uint32_t)__bfloat16_as_ushort(l0) | ((uint32_t)__bfloat16_as_ushort(l1) << 16);
}

// ---------------- fused multi-source bf16x3 GEMM + tanh ----------------
struct Srcs {
    const bf16* Ahi[5];
    const bf16* Alo[5];
    const int*  idx[5];
};

// smem: A planes [plane][buf][128][40 bf16] then B planes; 80B rows (64B data + 16B pad)
#define TILE_B   10240
#define SM_A     0
#define SM_B     40960
#define SMEM_BYTES 81920

__global__ void __launch_bounds__(256, 2)
k_mma(Srcs srcs, int ksrc, int cshift,
      const bf16* __restrict__ Whi, const bf16* __restrict__ Wlo, int Ktot,
      float* __restrict__ out_f32,
      bf16* __restrict__ out_hi, bf16* __restrict__ out_lo,
      bf16* __restrict__ out2_hi, bf16* __restrict__ out2_lo)
{
    extern __shared__ char smc[];
    const uint32_t smu = smem_u32(smc);

    const int tid  = threadIdx.x;
    const int lane = tid & 31;
    const int w    = tid >> 5;
    const int wm   = w & 3;      // 4 M-groups of 32 rows
    const int wn   = w >> 2;     // 2 N-groups of 64 cols
    const int lr   = lane >> 2;
    const int lc   = lane & 3;

    const int n0 = blockIdx.x * 128;
    const int m0 = blockIdx.y * 128;

    const int C     = Ktot >> 5;
    const int cmask = (ksrc >> 5) - 1;

    // ldmatrix lane-offset patterns (80B row stride)
    const int r8 = lane & 7, j8 = lane >> 3;
    const uint32_t offA = (uint32_t)((r8 + (j8 & 1) * 8) * 80 + ((j8 >> 1) & 1) * 16)
                        + (uint32_t)(wm * 32) * 80u;
    const uint32_t offB = (uint32_t)(r8 * 80 + ((j8 >> 1) & 1) * 640 + (j8 & 1) * 16)
                        + (uint32_t)(wn * 64) * 80u;

    // producer: thread -> (row = tid>>1, plane = tid&1); 64B per row per plane
    const int arow = tid >> 1;
    const int apl  = tid & 1;
    int cur_s = -1;
    const bf16* aptr = srcs.Ahi[0];
    const bf16* wbase = apl ? Wlo : Whi;

    auto load_chunk = [&](int c) {
        const int buf = c & 1;
        const int s = c >> cshift;
        if (s != cur_s) {
            cur_s = s;
            int gr = m0 + arow;
            const int* ix = srcs.idx[s];
            if (ix) gr = __ldg(ix + gr);
            aptr = (apl ? srcs.Alo[s] : srcs.Ahi[s]) + (size_t)gr * ksrc;
        }
        const bf16* as = aptr + ((c & cmask) << 5);
        const uint32_t ad = smu + (uint32_t)(SM_A + apl * 2 * TILE_B + buf * TILE_B + arow * 80);
        cp16(ad,      as);
        cp16(ad + 16, as + 8);
        cp16(ad + 32, as + 16);
        cp16(ad + 48, as + 24);
        const bf16* bs = wbase + (size_t)(n0 + arow) * Ktot + ((size_t)c << 5);
        const uint32_t bd = smu + (uint32_t)(SM_B + apl * 2 * TILE_B + buf * TILE_B + arow * 80);
        cp16(bd,      bs);
        cp16(bd + 16, bs + 8);
        cp16(bd + 32, bs + 16);
        cp16(bd + 48, bs + 24);
    };

    float acc[2][8][4];
#pragma unroll
    for (int mi = 0; mi < 2; mi++)
#pragma unroll
        for (int nj = 0; nj < 8; nj++)
#pragma unroll
            for (int q = 0; q < 4; q++) acc[mi][nj][q] = 0.f;

    load_chunk(0);
    CP_COMMIT();

    for (int c = 0; c < C; c++) {
        CP_WAIT0();
        __syncthreads();
        if (c + 1 < C) load_chunk(c + 1);
        CP_COMMIT();

        const int buf = c & 1;
        const uint32_t aH = smu + SM_A + (uint32_t)(buf * TILE_B);
        const uint32_t aL = aH + 2u * TILE_B;
        const uint32_t bH = smu + SM_B + (uint32_t)(buf * TILE_B);
        const uint32_t bL = bH + 2u * TILE_B;

#pragma unroll
        for (int ks = 0; ks < 2; ks++) {
            const uint32_t kb = (uint32_t)(ks * 32);
            uint32_t ah[2][4], al[2][4];
            ldsm4(ah[0], aH + offA + kb);
            ldsm4(ah[1], aH + offA + 1280u + kb);
            ldsm4(al[0], aL + offA + kb);
            ldsm4(al[1], aL + offA + 1280u + kb);
#pragma unroll
            for (int g = 0; g < 2; g++) {
                const uint32_t go = (uint32_t)(g * 2560);
                uint32_t bh[4][2], bl[4][2];
                ldsm4(&bh[0][0], bH + offB + go + kb);
                ldsm4(&bh[2][0], bH + offB + go + 1280u + kb);
                ldsm4(&bl[0][0], bL + offB + go + kb);
                ldsm4(&bl[2][0], bL + offB + go + 1280u + kb);
#pragma unroll
                for (int mi = 0; mi < 2; mi++)
#pragma unroll
                    for (int q = 0; q < 4; q++) {
                        float* acq = acc[mi][g * 4 + q];
                        mma_bf16(acq, ah[mi], bh[q]);
                        mma_bf16(acq, ah[mi], bl[q]);
                        mma_bf16(acq, al[mi], bh[q]);
                    }
            }
        }
        __syncthreads();
    }

    // epilogue
#pragma unroll
    for (int mi = 0; mi < 2; mi++) {
        const int r0 = m0 + wm * 32 + mi * 16 + lr;
#pragma unroll
        for (int nj = 0; nj < 8; nj++) {
            const int col = n0 + wn * 64 + nj * 8 + lc * 2;
            const float v0 = tanhf(acc[mi][nj][0]);
            const float v1 = tanhf(acc[mi][nj][1]);
            const float v2 = tanhf(acc[mi][nj][2]);
            const float v3 = tanhf(acc[mi][nj][3]);
            if (out_f32) {
                *(float2*)(out_f32 + (size_t)r0 * D + col)       = make_float2(v0, v1);
                *(float2*)(out_f32 + (size_t)(r0 + 8) * D + col) = make_float2(v2, v3);
            }
            if (out_hi) {
                uint32_t h01, l01, h23, l23;
                split2(v0, v1, h01, l01);
                split2(v2, v3, h23, l23);
                const size_t o0 = (size_t)r0 * D + col;
                const size_t o1 = (size_t)(r0 + 8) * D + col;
                *(uint32_t*)(out_hi + o0) = h01;  *(uint32_t*)(out_lo + o0) = l01;
                *(uint32_t*)(out_hi + o1) = h23;  *(uint32_t*)(out_lo + o1) = l23;
                if (out2_hi) {
                    *(uint32_t*)(out2_hi + o0) = h01;  *(uint32_t*)(out2_lo + o0) = l01;
                    *(uint32_t*)(out2_hi + o1) = h23;  *(uint32_t*)(out2_lo + o1) = l23;
                }
            }
        }
    }
}

// ---------------- small kernels ----------------
__global__ void k_offsets(const int* __restrict__ ids, int n, int* __restrict__ off)
{
    int m = blockIdx.x * blockDim.x + threadIdx.x;
    if (m > N_MOLS) return;
    int lo = 0, hi = n;
    while (lo < hi) {
        int mid = (lo + hi) >> 1;
        if (ids[mid] < m) lo = mid + 1; else hi = mid;
    }
    off[m] = lo;
}

__global__ void k_mol_mean(const float* __restrict__ atoms,
                           const int* __restrict__ aoff,
                           bf16* __restrict__ mhi, bf16* __restrict__ mlo)
{
    const int m = blockIdx.x, d = threadIdx.x;
    const int s = aoff[m], e = aoff[m + 1];
    float acc = 0.f;
    for (int i = s; i < e; i++) acc += atoms[(size_t)i * D_IN + d];
    float cnt = (float)(e - s);
    if (cnt < 1.f) cnt = 1.f;
    bf16 h, l;
    split1(acc / cnt, h, l);
    mhi[(size_t)m * D_IN + d] = h;
    mlo[(size_t)m * D_IN + d] = l;
}

__global__ void k_init_he0(const float* __restrict__ bo,
                           const float* __restrict__ Wfe,
                           bf16* __restrict__ e0hi, bf16* __restrict__ e0lo,
                           bf16* __restrict__ ehi,  bf16* __restrict__ elo)
{
    const int b = blockIdx.x, d = threadIdx.x * 2;
    const float o = bo[b];
    uint32_t h2, l2;
    split2(tanhf(o * Wfe[d]), tanhf(o * Wfe[d + 1]), h2, l2);
    const size_t off = (size_t)b * D + d;
    *(uint32_t*)(e0hi + off) = h2;  *(uint32_t*)(e0lo + off) = l2;
    *(uint32_t*)(ehi + off)  = h2;  *(uint32_t*)(elo + off)  = l2;
}

__global__ void k_scatter(const bf16* __restrict__ hehi, const bf16* __restrict__ helo,
                          const int* __restrict__ bsrc, const int* __restrict__ bdst,
                          float* __restrict__ ebv)
{
    const int t = blockIdx.x * blockDim.x + threadIdx.x;
    const int b = t >> 6;
    const int c4 = (t & 63) << 2;
    const size_t off = (size_t)b * D + c4;
    const __nv_bfloat162* h2 = (const __nv_bfloat162*)(hehi + off);
    const __nv_bfloat162* l2 = (const __nv_bfloat162*)(helo + off);
    float2 a0 = __bfloat1622float2(h2[0]), b0 = __bfloat1622float2(l2[0]);
    float2 a1 = __bfloat1622float2(h2[1]), b1 = __bfloat1622float2(l2[1]);
    float4 v = make_float4(a0.x + b0.x, a0.y + b0.y, a1.x + b1.x, a1.y + b1.y);
    const int s = __ldg(bsrc + b);
    const int d = __ldg(bdst + b);
    red4(ebv + (size_t)s * D + c4, v);
    red4(ebv + (size_t)d * D + c4, v);
}

__global__ void k_segsum(const bf16* __restrict__ xhi, const bf16* __restrict__ xlo,
                         const int* __restrict__ off,
                         bf16* __restrict__ ohi, bf16* __restrict__ olo)
{
    const int m = blockIdx.x, d = threadIdx.x;
    const int s = off[m], e = off[m + 1];
    float acc = 0.f;
    for (int i = s; i < e; i++) {
        const size_t o = (size_t)i * D + d;
        acc += __bfloat162float(xhi[o]) + __bfloat162float(xlo[o]);
    }
    bf16 h, l;
    split1(acc, h, l);
    ohi[(size_t)m * D + d] = h;
    olo[(size_t)m * D + d] = l;
}

__global__ void k_f2p(const float* __restrict__ in,
                      bf16* __restrict__ hi, bf16* __restrict__ lo, int n2)
{
    int i = blockIdx.x * blockDim.x + threadIdx.x;
    if (i >= n2) return;
    float2 v = ((const float2*)in)[i];
    uint32_t h2, l2;
    split2(v.x, v.y, h2, l2);
    ((uint32_t*)hi)[i] = h2;
    ((uint32_t*)lo)[i] = l2;
}

__global__ void k_transpose_planes(const float* __restrict__ W,
                                   bf16* __restrict__ Thi, bf16* __restrict__ Tlo, int K)
{
    __shared__ float t[32][33];
    const int k0 = blockIdx.x * 32, nb = blockIdx.y * 32;
    const int tx = threadIdx.x, ty = threadIdx.y;
#pragma unroll
    for (int i = 0; i < 4; i++)
        t[ty + 8 * i][tx] = W[(size_t)(k0 + ty + 8 * i) * D + nb + tx];
    __syncthreads();
#pragma unroll
    for (int i = 0; i < 4; i++) {
        bf16 h, l;
        split1(t[tx][ty + 8 * i], h, l);
        const size_t o = (size_t)(nb + ty + 8 * i) * K + k0 + tx;
        Thi[o] = h;
        Tlo[o] = l;
    }
}

// ---------------- host orchestration ----------------
static bf16* sym_bf16(const void* sym) {
    void* p = nullptr;
    cudaGetSymbolAddress(&p, sym);
    return (bf16*)p;
}

extern "C" void kernel_launch(void* const* d_in, const int* in_sizes, int n_in,
                              void* d_out, int out_size)
{
    const float* atoms       = (const float*)d_in[0];
    const float* bond_orders = (const float*)d_in[1];
    const int*   bond_src    = (const int*)  d_in[2];
    const int*   bond_dst    = (const int*)  d_in[3];
    const int*   atom_mol    = (const int*)  d_in[4];
    const int*   bond_mol    = (const int*)  d_in[5];
    const float* W_fe        = (const float*)d_in[6];
    const float* W_fv        = (const float*)d_in[7];
    const float* W_fu        = (const float*)d_in[8];
    const float* W_e         = (const float*)d_in[9];
    const float* W_v         = (const float*)d_in[10];
    const float* W_u         = (const float*)d_in[11];

    bf16* he_hi  = sym_bf16(g_he_hi);   bf16* he_lo  = sym_bf16(g_he_lo);
    bf16* he0_hi = sym_bf16(g_he0_hi);  bf16* he0_lo = sym_bf16(g_he0_lo);
    bf16* hv_hi  = sym_bf16(g_hv_hi);   bf16* hv_lo  = sym_bf16(g_hv_lo);
    bf16* hv0_hi = sym_bf16(g_hv0_hi);  bf16* hv0_lo = sym_bf16(g_hv0_lo);
    bf16* ebv_hi = sym_bf16(g_ebv_hi);  bf16* ebv_lo = sym_bf16(g_ebv_lo);
    bf16* hu_hi  = sym_bf16(g_hu_hi);   bf16* hu_lo  = sym_bf16(g_hu_lo);
    bf16* hu0_hi = sym_bf16(g_hu0_hi);  bf16* hu0_lo = sym_bf16(g_hu0_lo);
    bf16* ebar_hi= sym_bf16(g_ebar_hi); bf16* ebar_lo= sym_bf16(g_ebar_lo);
    bf16* vbar_hi= sym_bf16(g_vbar_hi); bf16* vbar_lo= sym_bf16(g_vbar_lo);
    bf16* mm_hi  = sym_bf16(g_mm_hi);   bf16* mm_lo  = sym_bf16(g_mm_lo);
    bf16* at_hi  = sym_bf16(g_at_hi);   bf16* at_lo  = sym_bf16(g_at_lo);
    bf16* we_hi  = sym_bf16(g_we_hi);   bf16* we_lo  = sym_bf16(g_we_lo);
    bf16* wv_hi  = sym_bf16(g_wv_hi);   bf16* wv_lo  = sym_bf16(g_wv_lo);
    bf16* wu_hi  = sym_bf16(g_wu_hi);   bf16* wu_lo  = sym_bf16(g_wu_lo);
    bf16* wfv_hi = sym_bf16(g_wfv_hi);  bf16* wfv_lo = sym_bf16(g_wfv_lo);
    bf16* wfu_hi = sym_bf16(g_wfu_hi);  bf16* wfu_lo = sym_bf16(g_wfu_lo);
    float* ebv_f = nullptr; { void* p; cudaGetSymbolAddress(&p, g_ebv_f); ebv_f = (float*)p; }
    int *boff, *aoff;
    { void* p; cudaGetSymbolAddress(&p, g_boff); boff = (int*)p; }
    { void* p; cudaGetSymbolAddress(&p, g_aoff); aoff = (int*)p; }

    const size_t SZ_E = (size_t)N_BONDS * D;
    const size_t SZ_V = (size_t)N_ATOMS * D;
    const size_t SZ_U = (size_t)N_MOLS * D;

    cudaFuncSetAttribute(k_mma, cudaFuncAttributeMaxDynamicSharedMemorySize, SMEM_BYTES);

    const int offBlocks = (N_MOLS + 1 + 255) / 256;
    k_offsets<<<offBlocks, 256>>>(bond_mol, N_BONDS, boff);
    k_offsets<<<offBlocks, 256>>>(atom_mol, N_ATOMS, aoff);

    k_transpose_planes<<<dim3(5 * D / 32, 8), dim3(32, 8)>>>(W_e,  we_hi,  we_lo,  5 * D);
    k_transpose_planes<<<dim3(4 * D / 32, 8), dim3(32, 8)>>>(W_v,  wv_hi,  wv_lo,  4 * D);
    k_transpose_planes<<<dim3(4 * D / 32, 8), dim3(32, 8)>>>(W_u,  wu_hi,  wu_lo,  4 * D);
    k_transpose_planes<<<dim3(D_IN / 32, 8),  dim3(32, 8)>>>(W_fv, wfv_hi, wfv_lo, D_IN);
    k_transpose_planes<<<dim3(D_IN / 32, 8),  dim3(32, 8)>>>(W_fu, wfu_hi, wfu_lo, D_IN);

    k_f2p<<<(int)((N_ATOMS * (size_t)D_IN / 2 + 255) / 256), 256>>>(atoms, at_hi, at_lo,
                                                                    N_ATOMS * D_IN / 2);
    k_init_he0<<<N_BONDS, 128>>>(bond_orders, W_fe, he0_hi, he0_lo, he_hi, he_lo);
    k_mol_mean<<<N_MOLS, 128>>>(atoms, aoff, mm_hi, mm_lo);

    {
        Srcs s = {};
        s.Ahi[0] = at_hi; s.Alo[0] = at_lo;
        k_mma<<<dim3(2, N_ATOMS / 128), 256, SMEM_BYTES>>>(
            s, D_IN, 2, wfv_hi, wfv_lo, D_IN,
            nullptr, hv0_hi, hv0_lo, hv_hi, hv_lo);
    }
    {
        Srcs s = {};
        s.Ahi[0] = mm_hi; s.Alo[0] = mm_lo;
        k_mma<<<dim3(2, N_MOLS / 128), 256, SMEM_BYTES>>>(
            s, D_IN, 2, wfu_hi, wfu_lo, D_IN,
            nullptr, hu0_hi, hu0_lo, hu_hi, hu_lo);
    }

    int ec = 0, vc = 0, uc = 0;

    for (int it = 0; it < 3; it++) {
        // edge update
        {
            Srcs s = {};
            s.Ahi[0] = he_hi + (size_t)ec * SZ_E;  s.Alo[0] = he_lo + (size_t)ec * SZ_E;
            s.Ahi[1] = he0_hi;                      s.Alo[1] = he0_lo;
            s.Ahi[2] = hv_hi + (size_t)vc * SZ_V;  s.Alo[2] = hv_lo + (size_t)vc * SZ_V;
            s.idx[2] = bond_src;
            s.Ahi[3] = s.Ahi[2];                    s.Alo[3] = s.Alo[2];
            s.idx[3] = bond_dst;
            s.Ahi[4] = hu_hi + (size_t)uc * SZ_U;  s.Alo[4] = hu_lo + (size_t)uc * SZ_U;
            s.idx[4] = bond_mol;
            if (it == 2) {
                k_mma<<<dim3(2, N_BONDS / 128), 256, SMEM_BYTES>>>(
                    s, D, 3, we_hi, we_lo, 5 * D,
                    (float*)d_out, nullptr, nullptr, nullptr, nullptr);
                break;
            }
            const int en = ec ^ 1;
            k_mma<<<dim3(2, N_BONDS / 128), 256, SMEM_BYTES>>>(
                s, D, 3, we_hi, we_lo, 5 * D,
                nullptr, he_hi + (size_t)en * SZ_E, he_lo + (size_t)en * SZ_E,
                nullptr, nullptr);
            ec = en;
        }

        cudaMemsetAsync(ebv_f, 0, SZ_V * sizeof(float), 0);
        k_scatter<<<N_BONDS * 64 / 256, 256>>>(he_hi + (size_t)ec * SZ_E,
                                               he_lo + (size_t)ec * SZ_E,
                                               bond_src, bond_dst, ebv_f);
        k_f2p<<<(int)((SZ_V / 2 + 255) / 256), 256>>>(ebv_f, ebv_hi, ebv_lo, (int)(SZ_V / 2));

        {
            Srcs s = {};
            s.Ahi[0] = hv_hi + (size_t)vc * SZ_V;  s.Alo[0] = hv_lo + (size_t)vc * SZ_V;
            s.Ahi[1] = hv0_hi;                      s.Alo[1] = hv0_lo;
            s.Ahi[2] = ebv_hi;                      s.Alo[2] = ebv_lo;
            s.Ahi[3] = hu_hi + (size_t)uc * SZ_U;  s.Alo[3] = hu_lo + (size_t)uc * SZ_U;
            s.idx[3] = atom_mol;
            const int vn = vc ^ 1;
            k_mma<<<dim3(2, N_ATOMS / 128), 256, SMEM_BYTES>>>(
                s, D, 3, wv_hi, wv_lo, 4 * D,
                nullptr, hv_hi + (size_t)vn * SZ_V, hv_lo + (size_t)vn * SZ_V,
                nullptr, nullptr);
            vc = vn;
        }

        k_segsum<<<N_MOLS, 256>>>(he_hi + (size_t)ec * SZ_E, he_lo + (size_t)ec * SZ_E,
                                  boff, ebar_hi, ebar_lo);
        k_segsum<<<N_MOLS, 256>>>(hv_hi + (size_t)vc * SZ_V, hv_lo + (size_t)vc * SZ_V,
                                  aoff, vbar_hi, vbar_lo);

        {
            Srcs s = {};
            s.Ahi[0] = hu_hi + (size_t)uc * SZ_U;  s.Alo[0] = hu_lo + (size_t)uc * SZ_U;
            s.Ahi[1] = hu0_hi;                      s.Alo[1] = hu0_lo;
            s.Ahi[2] = ebar_hi;                     s.Alo[2] = ebar_lo;
            s.Ahi[3] = vbar_hi;                     s.Alo[3] = vbar_lo;
            const int un = uc ^ 1;
            k_mma<<<dim3(2, N_MOLS / 128), 256, SMEM_BYTES>>>(
                s, D, 3, wu_hi, wu_lo, 4 * D,
                nullptr, hu_hi + (size_t)un * SZ_U, hu_lo + (size_t)un * SZ_U,
                nullptr, nullptr);
            uc = un;
        }
    }
}

// round 6
// speedup vs baseline: 2.0678x; 1.2786x over previous
#include <cuda_runtime.h>
#include <cuda_bf16.h>
#include <math.h>
#include <stdint.h>

typedef __nv_bfloat16 bf16;

#define N_ATOMS 65536
#define N_BONDS 98304
#define N_MOLS  4096
#define D_IN    128
#define D       256

// ---------------- scratch (device globals; no allocation allowed) ----------------
__device__ bf16 g_he_hi [2][(size_t)N_BONDS * D];
__device__ bf16 g_he_lo [2][(size_t)N_BONDS * D];
__device__ bf16 g_he0_hi[(size_t)N_BONDS * D];
__device__ bf16 g_he0_lo[(size_t)N_BONDS * D];
__device__ bf16 g_hv_hi [2][(size_t)N_ATOMS * D];
__device__ bf16 g_hv_lo [2][(size_t)N_ATOMS * D];
__device__ bf16 g_hv0_hi[(size_t)N_ATOMS * D];
__device__ bf16 g_hv0_lo[(size_t)N_ATOMS * D];
__device__ float g_ebv_f [(size_t)N_ATOMS * D];
__device__ bf16 g_ebv_hi[(size_t)N_ATOMS * D];
__device__ bf16 g_ebv_lo[(size_t)N_ATOMS * D];
__device__ bf16 g_hu_hi [2][(size_t)N_MOLS * D];
__device__ bf16 g_hu_lo [2][(size_t)N_MOLS * D];
__device__ bf16 g_hu0_hi[(size_t)N_MOLS * D];
__device__ bf16 g_hu0_lo[(size_t)N_MOLS * D];
__device__ bf16 g_ebar_hi[(size_t)N_MOLS * D];
__device__ bf16 g_ebar_lo[(size_t)N_MOLS * D];
__device__ bf16 g_vbar_hi[(size_t)N_MOLS * D];
__device__ bf16 g_vbar_lo[(size_t)N_MOLS * D];
__device__ bf16 g_mm_hi [(size_t)N_MOLS * D_IN];
__device__ bf16 g_mm_lo [(size_t)N_MOLS * D_IN];
__device__ bf16 g_at_hi [(size_t)N_ATOMS * D_IN];
__device__ bf16 g_at_lo [(size_t)N_ATOMS * D_IN];
__device__ bf16 g_we_hi [(size_t)D * 5 * D];
__device__ bf16 g_we_lo [(size_t)D * 5 * D];
__device__ bf16 g_wv_hi [(size_t)D * 4 * D];
__device__ bf16 g_wv_lo [(size_t)D * 4 * D];
__device__ bf16 g_wu_hi [(size_t)D * 4 * D];
__device__ bf16 g_wu_lo [(size_t)D * 4 * D];
__device__ bf16 g_wfv_hi[(size_t)D * D_IN];
__device__ bf16 g_wfv_lo[(size_t)D * D_IN];
__device__ bf16 g_wfu_hi[(size_t)D * D_IN];
__device__ bf16 g_wfu_lo[(size_t)D * D_IN];
// precomputed epilogue-add terms (fp32)
__device__ float g_E0 [(size_t)N_BONDS * D];   // he0 @ We[256:512]
__device__ float g_V0t[(size_t)N_ATOMS * D];   // hv0 @ Wv[256:512]
__device__ float g_Ue [(size_t)N_MOLS * D];    // hu  @ We[1024:1280]
__device__ float g_Uv [(size_t)N_MOLS * D];    // hu  @ Wv[768:1024]
__device__ int  g_boff[N_MOLS + 1];
__device__ int  g_aoff[N_MOLS + 1];

// ---------------- helpers ----------------
__device__ __forceinline__ uint32_t smem_u32(const void* p) {
    uint32_t a;
    asm("{ .reg .u64 t; cvta.to.shared.u64 t, %1; cvt.u32.u64 %0, t; }" : "=r"(a) : "l"(p));
    return a;
}
__device__ __forceinline__ void cp16(uint32_t dst, const void* src) {
    asm volatile("cp.async.cg.shared.global [%0], [%1], 16;" :: "r"(dst), "l"(src) : "memory");
}
#define CP_COMMIT()  asm volatile("cp.async.commit_group;" ::: "memory")
#define CP_WAIT0()   asm volatile("cp.async.wait_group 0;" ::: "memory")

__device__ __forceinline__ void ldsm4(uint32_t* r, uint32_t addr) {
    asm volatile("ldmatrix.sync.aligned.m8n8.x4.shared.b16 {%0,%1,%2,%3}, [%4];"
        : "=r"(r[0]), "=r"(r[1]), "=r"(r[2]), "=r"(r[3]) : "r"(addr));
}
__device__ __forceinline__ void mma_bf16(float* c, const uint32_t* a, const uint32_t* b) {
    asm volatile(
        "mma.sync.aligned.m16n8k16.row.col.f32.bf16.bf16.f32 "
        "{%0,%1,%2,%3}, {%4,%5,%6,%7}, {%8,%9}, {%0,%1,%2,%3};"
        : "+f"(c[0]), "+f"(c[1]), "+f"(c[2]), "+f"(c[3])
        : "r"(a[0]), "r"(a[1]), "r"(a[2]), "r"(a[3]), "r"(b[0]), "r"(b[1]));
}
__device__ __forceinline__ void red4(float* p, float4 v) {
    asm volatile("red.global.add.v4.f32 [%0], {%1,%2,%3,%4};"
        :: "l"(p), "f"(v.x), "f"(v.y), "f"(v.z), "f"(v.w) : "memory");
}
__device__ __forceinline__ void split1(float v, bf16& h, bf16& l) {
    h = __float2bfloat16(v);
    l = __float2bfloat16(v - __bfloat162float(h));
}
__device__ __forceinline__ void split2(float v0, float v1, uint32_t& h2, uint32_t& l2) {
    bf16 h0, l0, h1, l1;
    split1(v0, h0, l0);
    split1(v1, h1, l1);
    h2 = (uint32_t)__bfloat16_as_ushort(h0) | ((uint32_t)__bfloat16_as_ushort(h1) << 16);
    l2 = (uint32_t)__bfloat16_as_ushort(l0) | ((uint32_t)__bfloat16_as_ushort(l1) << 16);
}

// ---------------- fused multi-source bf16x3 GEMM (+adds, +tanh) ----------------
struct Srcs {
    const bf16* Ahi[4];
    const bf16* Alo[4];
    const int*  idx[4];
    int         wblk[4];   // weight K-block (x256) per source
};
struct Adds {
    const float* direct;   // [M x 256], indexed by global row
    const float* gat;      // [X x 256], indexed by gidx[row]
    const int*   gidx;
};

#define TILE_B   10240
#define SM_A     0
#define SM_B     40960
#define SMEM_BYTES 81920

__global__ void __launch_bounds__(256, 2)
k_mma(Srcs srcs, int ksrc, int cshift, int n_chunks,
      const bf16* __restrict__ Whi, const bf16* __restrict__ Wlo, int kstride,
      Adds adds, int do_tanh,
      float* __restrict__ out_f32,
      bf16* __restrict__ out_hi, bf16* __restrict__ out_lo,
      bf16* __restrict__ out2_hi, bf16* __restrict__ out2_lo)
{
    extern __shared__ char smc[];
    const uint32_t smu = smem_u32(smc);

    const int tid  = threadIdx.x;
    const int lane = tid & 31;
    const int w    = tid >> 5;
    const int wm   = w & 3;
    const int wn   = w >> 2;
    const int lr   = lane >> 2;
    const int lc   = lane & 3;

    const int n0 = blockIdx.x * 128;
    const int m0 = blockIdx.y * 128;

    const int cmask = (ksrc >> 5) - 1;

    const int r8 = lane & 7, j8 = lane >> 3;
    const uint32_t offA = (uint32_t)((r8 + (j8 & 1) * 8) * 80 + ((j8 >> 1) & 1) * 16)
                        + (uint32_t)(wm * 32) * 80u;
    const uint32_t offB = (uint32_t)(r8 * 80 + ((j8 >> 1) & 1) * 640 + (j8 & 1) * 16)
                        + (uint32_t)(wn * 64) * 80u;

    const int arow = tid >> 1;
    const int apl  = tid & 1;
    int cur_s = -1;
    const bf16* aptr = srcs.Ahi[0];
    const bf16* wbase = apl ? Wlo : Whi;

    auto load_chunk = [&](int c) {
        const int buf = c & 1;
        const int s = c >> cshift;
        if (s != cur_s) {
            cur_s = s;
            int gr = m0 + arow;
            const int* ix = srcs.idx[s];
            if (ix) gr = __ldg(ix + gr);
            aptr = (apl ? srcs.Alo[s] : srcs.Ahi[s]) + (size_t)gr * ksrc;
        }
        const bf16* as = aptr + ((c & cmask) << 5);
        const uint32_t ad = smu + (uint32_t)(SM_A + apl * 2 * TILE_B + buf * TILE_B + arow * 80);
        cp16(ad,      as);
        cp16(ad + 16, as + 8);
        cp16(ad + 32, as + 16);
        cp16(ad + 48, as + 24);
        const bf16* bs = wbase + (size_t)(n0 + arow) * kstride
                       + (srcs.wblk[s] << 8) + ((c & cmask) << 5);
        const uint32_t bd = smu + (uint32_t)(SM_B + apl * 2 * TILE_B + buf * TILE_B + arow * 80);
        cp16(bd,      bs);
        cp16(bd + 16, bs + 8);
        cp16(bd + 32, bs + 16);
        cp16(bd + 48, bs + 24);
    };

    float acc[2][8][4];
#pragma unroll
    for (int mi = 0; mi < 2; mi++)
#pragma unroll
        for (int nj = 0; nj < 8; nj++)
#pragma unroll
            for (int q = 0; q < 4; q++) acc[mi][nj][q] = 0.f;

    load_chunk(0);
    CP_COMMIT();

    for (int c = 0; c < n_chunks; c++) {
        CP_WAIT0();
        __syncthreads();
        if (c + 1 < n_chunks) load_chunk(c + 1);
        CP_COMMIT();

        const int buf = c & 1;
        const uint32_t aH = smu + SM_A + (uint32_t)(buf * TILE_B);
        const uint32_t aL = aH + 2u * TILE_B;
        const uint32_t bH = smu + SM_B + (uint32_t)(buf * TILE_B);
        const uint32_t bL = bH + 2u * TILE_B;

#pragma unroll
        for (int ks = 0; ks < 2; ks++) {
            const uint32_t kb = (uint32_t)(ks * 32);
            uint32_t ah[2][4], al[2][4];
            ldsm4(ah[0], aH + offA + kb);
            ldsm4(ah[1], aH + offA + 1280u + kb);
            ldsm4(al[0], aL + offA + kb);
            ldsm4(al[1], aL + offA + 1280u + kb);
#pragma unroll
            for (int g = 0; g < 2; g++) {
                const uint32_t go = (uint32_t)(g * 2560);
                uint32_t bh[4][2], bl[4][2];
                ldsm4(&bh[0][0], bH + offB + go + kb);
                ldsm4(&bh[2][0], bH + offB + go + 1280u + kb);
                ldsm4(&bl[0][0], bL + offB + go + kb);
                ldsm4(&bl[2][0], bL + offB + go + 1280u + kb);
#pragma unroll
                for (int mi = 0; mi < 2; mi++)
#pragma unroll
                    for (int q = 0; q < 4; q++) {
                        float* acq = acc[mi][g * 4 + q];
                        mma_bf16(acq, ah[mi], bh[q]);
                        mma_bf16(acq, ah[mi], bl[q]);
                        mma_bf16(acq, al[mi], bh[q]);
                    }
            }
        }
        __syncthreads();
    }

    // epilogue
#pragma unroll
    for (int mi = 0; mi < 2; mi++) {
        const int r0 = m0 + wm * 32 + mi * 16 + lr;
        const int r1 = r0 + 8;
        const float* d0 = adds.direct ? adds.direct + (size_t)r0 * D : nullptr;
        const float* d1 = adds.direct ? adds.direct + (size_t)r1 * D : nullptr;
        const float* g0 = nullptr;
        const float* g1 = nullptr;
        if (adds.gat) {
            g0 = adds.gat + (size_t)__ldg(adds.gidx + r0) * D;
            g1 = adds.gat + (size_t)__ldg(adds.gidx + r1) * D;
        }
#pragma unroll
        for (int nj = 0; nj < 8; nj++) {
            const int col = n0 + wn * 64 + nj * 8 + lc * 2;
            float v0 = acc[mi][nj][0];
            float v1 = acc[mi][nj][1];
            float v2 = acc[mi][nj][2];
            float v3 = acc[mi][nj][3];
            if (d0) {
                float2 t0 = *(const float2*)(d0 + col);
                float2 t1 = *(const float2*)(d1 + col);
                v0 += t0.x; v1 += t0.y; v2 += t1.x; v3 += t1.y;
            }
            if (g0) {
                float2 t0 = *(const float2*)(g0 + col);
                float2 t1 = *(const float2*)(g1 + col);
                v0 += t0.x; v1 += t0.y; v2 += t1.x; v3 += t1.y;
            }
            if (do_tanh) {
                v0 = tanhf(v0); v1 = tanhf(v1); v2 = tanhf(v2); v3 = tanhf(v3);
            }
            if (out_f32) {
                *(float2*)(out_f32 + (size_t)r0 * D + col) = make_float2(v0, v1);
                *(float2*)(out_f32 + (size_t)r1 * D + col) = make_float2(v2, v3);
            }
            if (out_hi) {
                uint32_t h01, l01, h23, l23;
                split2(v0, v1, h01, l01);
                split2(v2, v3, h23, l23);
                const size_t o0 = (size_t)r0 * D + col;
                const size_t o1 = (size_t)r1 * D + col;
                *(uint32_t*)(out_hi + o0) = h01;  *(uint32_t*)(out_lo + o0) = l01;
                *(uint32_t*)(out_hi + o1) = h23;  *(uint32_t*)(out_lo + o1) = l23;
                if (out2_hi) {
                    *(uint32_t*)(out2_hi + o0) = h01;  *(uint32_t*)(out2_lo + o0) = l01;
                    *(uint32_t*)(out2_hi + o1) = h23;  *(uint32_t*)(out2_lo + o1) = l23;
                }
            }
        }
    }
}

// ---------------- small kernels ----------------
__global__ void k_offsets(const int* __restrict__ ids, int n, int* __restrict__ off)
{
    int m = blockIdx.x * blockDim.x + threadIdx.x;
    if (m > N_MOLS) return;
    int lo = 0, hi = n;
    while (lo < hi) {
        int mid = (lo + hi) >> 1;
        if (ids[mid] < m) lo = mid + 1; else hi = mid;
    }
    off[m] = lo;
}

__global__ void k_mol_mean(const float* __restrict__ atoms,
                           const int* __restrict__ aoff,
                           bf16* __restrict__ mhi, bf16* __restrict__ mlo)
{
    const int m = blockIdx.x, d = threadIdx.x;
    const int s = aoff[m], e = aoff[m + 1];
    float acc = 0.f;
    for (int i = s; i < e; i++) acc += atoms[(size_t)i * D_IN + d];
    float cnt = (float)(e - s);
    if (cnt < 1.f) cnt = 1.f;
    bf16 h, l;
    split1(acc / cnt, h, l);
    mhi[(size_t)m * D_IN + d] = h;
    mlo[(size_t)m * D_IN + d] = l;
}

__global__ void k_init_he0(const float* __restrict__ bo,
                           const float* __restrict__ Wfe,
                           bf16* __restrict__ e0hi, bf16* __restrict__ e0lo,
                           bf16* __restrict__ ehi,  bf16* __restrict__ elo)
{
    const int b = blockIdx.x, d = threadIdx.x * 2;
    const float o = bo[b];
    uint32_t h2, l2;
    split2(tanhf(o * Wfe[d]), tanhf(o * Wfe[d + 1]), h2, l2);
    const size_t off = (size_t)b * D + d;
    *(uint32_t*)(e0hi + off) = h2;  *(uint32_t*)(e0lo + off) = l2;
    *(uint32_t*)(ehi + off)  = h2;  *(uint32_t*)(elo + off)  = l2;
}

__global__ void k_scatter(const bf16* __restrict__ hehi, const bf16* __restrict__ helo,
                          const int* __restrict__ bsrc, const int* __restrict__ bdst,
                          float* __restrict__ ebv)
{
    const int t = blockIdx.x * blockDim.x + threadIdx.x;
    const int b = t >> 6;
    const int c4 = (t & 63) << 2;
    const size_t off = (size_t)b * D + c4;
    const __nv_bfloat162* h2 = (const __nv_bfloat162*)(hehi + off);
    const __nv_bfloat162* l2 = (const __nv_bfloat162*)(helo + off);
    float2 a0 = __bfloat1622float2(h2[0]), b0 = __bfloat1622float2(l2[0]);
    float2 a1 = __bfloat1622float2(h2[1]), b1 = __bfloat1622float2(l2[1]);
    float4 v = make_float4(a0.x + b0.x, a0.y + b0.y, a1.x + b1.x, a1.y + b1.y);
    const int s = __ldg(bsrc + b);
    const int d = __ldg(bdst + b);
    red4(ebv + (size_t)s * D + c4, v);
    red4(ebv + (size_t)d * D + c4, v);
}

__global__ void k_segsum(const bf16* __restrict__ xhi, const bf16* __restrict__ xlo,
                         const int* __restrict__ off,
                         bf16* __restrict__ ohi, bf16* __restrict__ olo)
{
    const int m = blockIdx.x, d = threadIdx.x;
    const int s = off[m], e = off[m + 1];
    float acc = 0.f;
    for (int i = s; i < e; i++) {
        const size_t o = (size_t)i * D + d;
        acc += __bfloat162float(xhi[o]) + __bfloat162float(xlo[o]);
    }
    bf16 h, l;
    split1(acc, h, l);
    ohi[(size_t)m * D + d] = h;
    olo[(size_t)m * D + d] = l;
}

__global__ void k_f2p(const float* __restrict__ in,
                      bf16* __restrict__ hi, bf16* __restrict__ lo, int n2)
{
    int i = blockIdx.x * blockDim.x + threadIdx.x;
    if (i >= n2) return;
    float2 v = ((const float2*)in)[i];
    uint32_t h2, l2;
    split2(v.x, v.y, h2, l2);
    ((uint32_t*)hi)[i] = h2;
    ((uint32_t*)lo)[i] = l2;
}

__global__ void k_transpose_planes(const float* __restrict__ W,
                                   bf16* __restrict__ Thi, bf16* __restrict__ Tlo, int K)
{
    __shared__ float t[32][33];
    const int k0 = blockIdx.x * 32, nb = blockIdx.y * 32;
    const int tx = threadIdx.x, ty = threadIdx.y;
#pragma unroll
    for (int i = 0; i < 4; i++)
        t[ty + 8 * i][tx] = W[(size_t)(k0 + ty + 8 * i) * D + nb + tx];
    __syncthreads();
#pragma unroll
    for (int i = 0; i < 4; i++) {
        bf16 h, l;
        split1(t[tx][ty + 8 * i], h, l);
        const size_t o = (size_t)(nb + ty + 8 * i) * K + k0 + tx;
        Thi[o] = h;
        Tlo[o] = l;
    }
}

// ---------------- host orchestration ----------------
static bf16* sym_bf16(const void* sym) {
    void* p = nullptr;
    cudaGetSymbolAddress(&p, sym);
    return (bf16*)p;
}
static float* sym_f32(const void* sym) {
    void* p = nullptr;
    cudaGetSymbolAddress(&p, sym);
    return (float*)p;
}

extern "C" void kernel_launch(void* const* d_in, const int* in_sizes, int n_in,
                              void* d_out, int out_size)
{
    const float* atoms       = (const float*)d_in[0];
    const float* bond_orders = (const float*)d_in[1];
    const int*   bond_src    = (const int*)  d_in[2];
    const int*   bond_dst    = (const int*)  d_in[3];
    const int*   atom_mol    = (const int*)  d_in[4];
    const int*   bond_mol    = (const int*)  d_in[5];
    const float* W_fe        = (const float*)d_in[6];
    const float* W_fv        = (const float*)d_in[7];
    const float* W_fu        = (const float*)d_in[8];
    const float* W_e         = (const float*)d_in[9];
    const float* W_v         = (const float*)d_in[10];
    const float* W_u         = (const float*)d_in[11];

    bf16* he_hi  = sym_bf16(g_he_hi);   bf16* he_lo  = sym_bf16(g_he_lo);
    bf16* he0_hi = sym_bf16(g_he0_hi);  bf16* he0_lo = sym_bf16(g_he0_lo);
    bf16* hv_hi  = sym_bf16(g_hv_hi);   bf16* hv_lo  = sym_bf16(g_hv_lo);
    bf16* hv0_hi = sym_bf16(g_hv0_hi);  bf16* hv0_lo = sym_bf16(g_hv0_lo);
    bf16* ebv_hi = sym_bf16(g_ebv_hi);  bf16* ebv_lo = sym_bf16(g_ebv_lo);
    bf16* hu_hi  = sym_bf16(g_hu_hi);   bf16* hu_lo  = sym_bf16(g_hu_lo);
    bf16* hu0_hi = sym_bf16(g_hu0_hi);  bf16* hu0_lo = sym_bf16(g_hu0_lo);
    bf16* ebar_hi= sym_bf16(g_ebar_hi); bf16* ebar_lo= sym_bf16(g_ebar_lo);
    bf16* vbar_hi= sym_bf16(g_vbar_hi); bf16* vbar_lo= sym_bf16(g_vbar_lo);
    bf16* mm_hi  = sym_bf16(g_mm_hi);   bf16* mm_lo  = sym_bf16(g_mm_lo);
    bf16* at_hi  = sym_bf16(g_at_hi);   bf16* at_lo  = sym_bf16(g_at_lo);
    bf16* we_hi  = sym_bf16(g_we_hi);   bf16* we_lo  = sym_bf16(g_we_lo);
    bf16* wv_hi  = sym_bf16(g_wv_hi);   bf16* wv_lo  = sym_bf16(g_wv_lo);
    bf16* wu_hi  = sym_bf16(g_wu_hi);   bf16* wu_lo  = sym_bf16(g_wu_lo);
    bf16* wfv_hi = sym_bf16(g_wfv_hi);  bf16* wfv_lo = sym_bf16(g_wfv_lo);
    bf16* wfu_hi = sym_bf16(g_wfu_hi);  bf16* wfu_lo = sym_bf16(g_wfu_lo);
    float* ebv_f = sym_f32(g_ebv_f);
    float* E0    = sym_f32(g_E0);
    float* V0t   = sym_f32(g_V0t);
    float* Ue    = sym_f32(g_Ue);
    float* Uv    = sym_f32(g_Uv);
    int *boff, *aoff;
    { void* p; cudaGetSymbolAddress(&p, g_boff); boff = (int*)p; }
    { void* p; cudaGetSymbolAddress(&p, g_aoff); aoff = (int*)p; }

    const size_t SZ_E = (size_t)N_BONDS * D;
    const size_t SZ_V = (size_t)N_ATOMS * D;
    const size_t SZ_U = (size_t)N_MOLS * D;

    cudaFuncSetAttribute(k_mma, cudaFuncAttributeMaxDynamicSharedMemorySize, SMEM_BYTES);

    const Adds noadd = {nullptr, nullptr, nullptr};

    const int offBlocks = (N_MOLS + 1 + 255) / 256;
    k_offsets<<<offBlocks, 256>>>(bond_mol, N_BONDS, boff);
    k_offsets<<<offBlocks, 256>>>(atom_mol, N_ATOMS, aoff);

    k_transpose_planes<<<dim3(5 * D / 32, 8), dim3(32, 8)>>>(W_e,  we_hi,  we_lo,  5 * D);
    k_transpose_planes<<<dim3(4 * D / 32, 8), dim3(32, 8)>>>(W_v,  wv_hi,  wv_lo,  4 * D);
    k_transpose_planes<<<dim3(4 * D / 32, 8), dim3(32, 8)>>>(W_u,  wu_hi,  wu_lo,  4 * D);
    k_transpose_planes<<<dim3(D_IN / 32, 8),  dim3(32, 8)>>>(W_fv, wfv_hi, wfv_lo, D_IN);
    k_transpose_planes<<<dim3(D_IN / 32, 8),  dim3(32, 8)>>>(W_fu, wfu_hi, wfu_lo, D_IN);

    k_f2p<<<(int)((N_ATOMS * (size_t)D_IN / 2 + 255) / 256), 256>>>(atoms, at_hi, at_lo,
                                                                    N_ATOMS * D_IN / 2);
    k_init_he0<<<N_BONDS, 128>>>(bond_orders, W_fe, he0_hi, he0_lo, he_hi, he_lo);
    k_mol_mean<<<N_MOLS, 128>>>(atoms, aoff, mm_hi, mm_lo);

    // h_v0 = tanh(atoms @ W_fv); seed h_v
    {
        Srcs s = {};
        s.Ahi[0] = at_hi; s.Alo[0] = at_lo; s.wblk[0] = 0;
        k_mma<<<dim3(2, N_ATOMS / 128), 256, SMEM_BYTES>>>(
            s, D_IN, 2, 4, wfv_hi, wfv_lo, D_IN, noadd, 1,
            nullptr, hv0_hi, hv0_lo, hv_hi, hv_lo);
    }
    // h_u0 = tanh(mol_mean @ W_fu); seed h_u
    {
        Srcs s = {};
        s.Ahi[0] = mm_hi; s.Alo[0] = mm_lo; s.wblk[0] = 0;
        k_mma<<<dim3(2, N_MOLS / 128), 256, SMEM_BYTES>>>(
            s, D_IN, 2, 4, wfu_hi, wfu_lo, D_IN, noadd, 1,
            nullptr, hu0_hi, hu0_lo, hu_hi, hu_lo);
    }
    // E0 = he0 @ We[256:512]  (raw fp32, no tanh)
    {
        Srcs s = {};
        s.Ahi[0] = he0_hi; s.Alo[0] = he0_lo; s.wblk[0] = 1;
        k_mma<<<dim3(2, N_BONDS / 128), 256, SMEM_BYTES>>>(
            s, D, 3, 8, we_hi, we_lo, 5 * D, noadd, 0,
            E0, nullptr, nullptr, nullptr, nullptr);
    }
    // V0t = hv0 @ Wv[256:512]
    {
        Srcs s = {};
        s.Ahi[0] = hv0_hi; s.Alo[0] = hv0_lo; s.wblk[0] = 1;
        k_mma<<<dim3(2, N_ATOMS / 128), 256, SMEM_BYTES>>>(
            s, D, 3, 8, wv_hi, wv_lo, 4 * D, noadd, 0,
            V0t, nullptr, nullptr, nullptr, nullptr);
    }

    int ec = 0, vc = 0, uc = 0;

    for (int it = 0; it < 3; it++) {
        // Ue = hu @ We[1024:1280] on mol rows
        {
            Srcs s = {};
            s.Ahi[0] = hu_hi + (size_t)uc * SZ_U; s.Alo[0] = hu_lo + (size_t)uc * SZ_U;
            s.wblk[0] = 4;
            k_mma<<<dim3(2, N_MOLS / 128), 256, SMEM_BYTES>>>(
                s, D, 3, 8, we_hi, we_lo, 5 * D, noadd, 0,
                Ue, nullptr, nullptr, nullptr, nullptr);
        }
        // edge update: 3 sources (he, hv[src], hv[dst]); adds E0 + Ue[bond_mol]
        {
            Srcs s = {};
            s.Ahi[0] = he_hi + (size_t)ec * SZ_E;  s.Alo[0] = he_lo + (size_t)ec * SZ_E;
            s.wblk[0] = 0;
            s.Ahi[1] = hv_hi + (size_t)vc * SZ_V;  s.Alo[1] = hv_lo + (size_t)vc * SZ_V;
            s.idx[1] = bond_src;  s.wblk[1] = 2;
            s.Ahi[2] = s.Ahi[1];                    s.Alo[2] = s.Alo[1];
            s.idx[2] = bond_dst;  s.wblk[2] = 3;
            Adds a = {E0, Ue, bond_mol};
            if (it == 2) {
                k_mma<<<dim3(2, N_BONDS / 128), 256, SMEM_BYTES>>>(
                    s, D, 3, 24, we_hi, we_lo, 5 * D, a, 1,
                    (float*)d_out, nullptr, nullptr, nullptr, nullptr);
                break;
            }
            const int en = ec ^ 1;
            k_mma<<<dim3(2, N_BONDS / 128), 256, SMEM_BYTES>>>(
                s, D, 3, 24, we_hi, we_lo, 5 * D, a, 1,
                nullptr, he_hi + (size_t)en * SZ_E, he_lo + (size_t)en * SZ_E,
                nullptr, nullptr);
            ec = en;
        }

        cudaMemsetAsync(ebv_f, 0, SZ_V * sizeof(float), 0);
        k_scatter<<<N_BONDS * 64 / 256, 256>>>(he_hi + (size_t)ec * SZ_E,
                                               he_lo + (size_t)ec * SZ_E,
                                               bond_src, bond_dst, ebv_f);
        k_f2p<<<(int)((SZ_V / 2 + 255) / 256), 256>>>(ebv_f, ebv_hi, ebv_lo, (int)(SZ_V / 2));

        // Uv = hu @ Wv[768:1024]
        {
            Srcs s = {};
            s.Ahi[0] = hu_hi + (size_t)uc * SZ_U; s.Alo[0] = hu_lo + (size_t)uc * SZ_U;
            s.wblk[0] = 3;
            k_mma<<<dim3(2, N_MOLS / 128), 256, SMEM_BYTES>>>(
                s, D, 3, 8, wv_hi, wv_lo, 4 * D, noadd, 0,
                Uv, nullptr, nullptr, nullptr, nullptr);
        }
        // node update: 2 sources (hv, ebv); adds V0t + Uv[atom_mol]
        {
            Srcs s = {};
            s.Ahi[0] = hv_hi + (size_t)vc * SZ_V;  s.Alo[0] = hv_lo + (size_t)vc * SZ_V;
            s.wblk[0] = 0;
            s.Ahi[1] = ebv_hi;                      s.Alo[1] = ebv_lo;
            s.wblk[1] = 2;
            Adds a = {V0t, Uv, atom_mol};
            const int vn = vc ^ 1;
            k_mma<<<dim3(2, N_ATOMS / 128), 256, SMEM_BYTES>>>(
                s, D, 3, 16, wv_hi, wv_lo, 4 * D, a, 1,
                nullptr, hv_hi + (size_t)vn * SZ_V, hv_lo + (size_t)vn * SZ_V,
                nullptr, nullptr);
            vc = vn;
        }

        k_segsum<<<N_MOLS, 256>>>(he_hi + (size_t)ec * SZ_E, he_lo + (size_t)ec * SZ_E,
                                  boff, ebar_hi, ebar_lo);
        k_segsum<<<N_MOLS, 256>>>(hv_hi + (size_t)vc * SZ_V, hv_lo + (size_t)vc * SZ_V,
                                  aoff, vbar_hi, vbar_lo);

        // global update: 4 sources
        {
            Srcs s = {};
            s.Ahi[0] = hu_hi + (size_t)uc * SZ_U;  s.Alo[0] = hu_lo + (size_t)uc * SZ_U;
            s.wblk[0] = 0;
            s.Ahi[1] = hu0_hi;                      s.Alo[1] = hu0_lo;
            s.wblk[1] = 1;
            s.Ahi[2] = ebar_hi;                     s.Alo[2] = ebar_lo;
            s.wblk[2] = 2;
            s.Ahi[3] = vbar_hi;                     s.Alo[3] = vbar_lo;
            s.wblk[3] = 3;
            const int un = uc ^ 1;
            k_mma<<<dim3(2, N_MOLS / 128), 256, SMEM_BYTES>>>(
                s, D, 3, 32, wu_hi, wu_lo, 4 * D, noadd, 1,
                nullptr, hu_hi + (size_t)un * SZ_U, hu_lo + (size_t)un * SZ_U,
                nullptr, nullptr);
            uc = un;
        }
    }
}

// round 7
// speedup vs baseline: 2.1212x; 1.0258x over previous
#include <cuda_runtime.h>
#include <cuda_bf16.h>
#include <math.h>
#include <stdint.h>

typedef __nv_bfloat16 bf16;

#define N_ATOMS 65536
#define N_BONDS 98304
#define N_MOLS  4096
#define D_IN    128
#define D       256

// ---------------- scratch (device globals; no allocation allowed) ----------------
__device__ bf16 g_he_hi [2][(size_t)N_BONDS * D];
__device__ bf16 g_he_lo [2][(size_t)N_BONDS * D];
__device__ bf16 g_he0_hi[(size_t)N_BONDS * D];
__device__ bf16 g_he0_lo[(size_t)N_BONDS * D];
__device__ bf16 g_hv_hi [2][(size_t)N_ATOMS * D];
__device__ bf16 g_hv_lo [2][(size_t)N_ATOMS * D];
__device__ bf16 g_hv0_hi[(size_t)N_ATOMS * D];
__device__ bf16 g_hv0_lo[(size_t)N_ATOMS * D];
__device__ float g_ebv_f [(size_t)N_ATOMS * D];
__device__ bf16 g_ebv_hi[(size_t)N_ATOMS * D];
__device__ bf16 g_ebv_lo[(size_t)N_ATOMS * D];
__device__ bf16 g_hu_hi [2][(size_t)N_MOLS * D];
__device__ bf16 g_hu_lo [2][(size_t)N_MOLS * D];
__device__ bf16 g_hu0_hi[(size_t)N_MOLS * D];
__device__ bf16 g_hu0_lo[(size_t)N_MOLS * D];
__device__ bf16 g_ebar_hi[(size_t)N_MOLS * D];
__device__ bf16 g_ebar_lo[(size_t)N_MOLS * D];
__device__ bf16 g_vbar_hi[(size_t)N_MOLS * D];
__device__ bf16 g_vbar_lo[(size_t)N_MOLS * D];
__device__ bf16 g_mm_hi [(size_t)N_MOLS * D_IN];
__device__ bf16 g_mm_lo [(size_t)N_MOLS * D_IN];
__device__ bf16 g_at_hi [(size_t)N_ATOMS * D_IN];
__device__ bf16 g_at_lo [(size_t)N_ATOMS * D_IN];
__device__ bf16 g_we_hi [(size_t)D * 5 * D];
__device__ bf16 g_we_lo [(size_t)D * 5 * D];
__device__ bf16 g_wv_hi [(size_t)D * 4 * D];
__device__ bf16 g_wv_lo [(size_t)D * 4 * D];
__device__ bf16 g_wu_hi [(size_t)D * 4 * D];
__device__ bf16 g_wu_lo [(size_t)D * 4 * D];
__device__ bf16 g_wfv_hi[(size_t)D * D_IN];
__device__ bf16 g_wfv_lo[(size_t)D * D_IN];
__device__ bf16 g_wfu_hi[(size_t)D * D_IN];
__device__ bf16 g_wfu_lo[(size_t)D * D_IN];
// precomputed fp32 epilogue-add terms
__device__ float g_E0 [(size_t)N_BONDS * D];   // he0 @ We[256:512]
__device__ float g_V0t[(size_t)N_ATOMS * D];   // hv0 @ Wv[256:512]
__device__ float g_Ue [(size_t)N_MOLS * D];    // hu  @ We[1024:1280]
__device__ float g_Uv [(size_t)N_MOLS * D];    // hu  @ Wv[768:1024]
__device__ float g_Vs [(size_t)N_ATOMS * D];   // hv  @ We[512:768]
__device__ float g_Vd [(size_t)N_ATOMS * D];   // hv  @ We[768:1024]
__device__ int  g_boff[N_MOLS + 1];
__device__ int  g_aoff[N_MOLS + 1];

// ---------------- helpers ----------------
__device__ __forceinline__ uint32_t smem_u32(const void* p) {
    uint32_t a;
    asm("{ .reg .u64 t; cvta.to.shared.u64 t, %1; cvt.u32.u64 %0, t; }" : "=r"(a) : "l"(p));
    return a;
}
__device__ __forceinline__ void cp16(uint32_t dst, const void* src) {
    asm volatile("cp.async.cg.shared.global [%0], [%1], 16;" :: "r"(dst), "l"(src) : "memory");
}
#define CP_COMMIT()  asm volatile("cp.async.commit_group;" ::: "memory")
#define CP_WAIT0()   asm volatile("cp.async.wait_group 0;" ::: "memory")

__device__ __forceinline__ void ldsm4(uint32_t* r, uint32_t addr) {
    asm volatile("ldmatrix.sync.aligned.m8n8.x4.shared.b16 {%0,%1,%2,%3}, [%4];"
        : "=r"(r[0]), "=r"(r[1]), "=r"(r[2]), "=r"(r[3]) : "r"(addr));
}
__device__ __forceinline__ void mma_bf16(float* c, const uint32_t* a, const uint32_t* b) {
    asm volatile(
        "mma.sync.aligned.m16n8k16.row.col.f32.bf16.bf16.f32 "
        "{%0,%1,%2,%3}, {%4,%5,%6,%7}, {%8,%9}, {%0,%1,%2,%3};"
        : "+f"(c[0]), "+f"(c[1]), "+f"(c[2]), "+f"(c[3])
        : "r"(a[0]), "r"(a[1]), "r"(a[2]), "r"(a[3]), "r"(b[0]), "r"(b[1]));
}
__device__ __forceinline__ void red2(float* p, float a, float b) {
    asm volatile("red.global.add.v2.f32 [%0], {%1,%2};"
        :: "l"(p), "f"(a), "f"(b) : "memory");
}
__device__ __forceinline__ void split1(float v, bf16& h, bf16& l) {
    h = __float2bfloat16(v);
    l = __float2bfloat16(v - __bfloat162float(h));
}
__device__ __forceinline__ void split2(float v0, float v1, uint32_t& h2, uint32_t& l2) {
    bf16 h0, l0, h1, l1;
    split1(v0, h0, l0);
    split1(v1, h1, l1);
    h2 = (uint32_t)__bfloat16_as_ushort(h0) | ((uint32_t)__bfloat16_as_ushort(h1) << 16);
    l2 = (uint32_t)__bfloat16_as_ushort(l0) | ((uint32_t)__bfloat16_as_ushort(l1) << 16);
}

// ---------------- fused multi-source bf16x3 GEMM (+adds, +scatter, +tanh) ---------
struct Srcs {
    const bf16* Ahi[4];
    const bf16* Alo[4];
    const int*  idx[4];
    int         wblk[4];
};
struct Adds {
    const float* direct;
    const float* gat[3];
    const int*   gidx[3];
};
struct Scat {
    float*     buf;
    const int* i0;
    const int* i1;
};

#define TILE_B   10240
#define SM_A     0
#define SM_B     40960
#define SMEM_BYTES 81920

__global__ void __launch_bounds__(256, 2)
k_mma(Srcs srcs, int ksrc, int cshift, int n_chunks,
      const bf16* __restrict__ Whi, const bf16* __restrict__ Wlo, int kstride,
      Adds adds, Scat scat, int do_tanh,
      float* __restrict__ out_f32,
      bf16* __restrict__ out_hi, bf16* __restrict__ out_lo,
      bf16* __restrict__ out2_hi, bf16* __restrict__ out2_lo)
{
    extern __shared__ char smc[];
    const uint32_t smu = smem_u32(smc);

    const int tid  = threadIdx.x;
    const int lane = tid & 31;
    const int w    = tid >> 5;
    const int wm   = w & 3;
    const int wn   = w >> 2;
    const int lr   = lane >> 2;
    const int lc   = lane & 3;

    const int n0 = blockIdx.x * 128;
    const int m0 = blockIdx.y * 128;

    const int cmask = (ksrc >> 5) - 1;

    const int r8 = lane & 7, j8 = lane >> 3;
    const uint32_t offA = (uint32_t)((r8 + (j8 & 1) * 8) * 80 + ((j8 >> 1) & 1) * 16)
                        + (uint32_t)(wm * 32) * 80u;
    const uint32_t offB = (uint32_t)(r8 * 80 + ((j8 >> 1) & 1) * 640 + (j8 & 1) * 16)
                        + (uint32_t)(wn * 64) * 80u;

    const int arow = tid >> 1;
    const int apl  = tid & 1;
    int cur_s = -1;
    const bf16* aptr = srcs.Ahi[0];
    const bf16* wbase = apl ? Wlo : Whi;

    auto load_chunk = [&](int c) {
        const int buf = c & 1;
        const int s = c >> cshift;
        if (s != cur_s) {
            cur_s = s;
            int gr = m0 + arow;
            const int* ix = srcs.idx[s];
            if (ix) gr = __ldg(ix + gr);
            aptr = (apl ? srcs.Alo[s] : srcs.Ahi[s]) + (size_t)gr * ksrc;
        }
        const bf16* as = aptr + ((c & cmask) << 5);
        const uint32_t ad = smu + (uint32_t)(SM_A + apl * 2 * TILE_B + buf * TILE_B + arow * 80);
        cp16(ad,      as);
        cp16(ad + 16, as + 8);
        cp16(ad + 32, as + 16);
        cp16(ad + 48, as + 24);
        const bf16* bs = wbase + (size_t)(n0 + arow) * kstride
                       + (srcs.wblk[s] << 8) + ((c & cmask) << 5);
        const uint32_t bd = smu + (uint32_t)(SM_B + apl * 2 * TILE_B + buf * TILE_B + arow * 80);
        cp16(bd,      bs);
        cp16(bd + 16, bs + 8);
        cp16(bd + 32, bs + 16);
        cp16(bd + 48, bs + 24);
    };

    float acc[2][8][4];
#pragma unroll
    for (int mi = 0; mi < 2; mi++)
#pragma unroll
        for (int nj = 0; nj < 8; nj++)
#pragma unroll
            for (int q = 0; q < 4; q++) acc[mi][nj][q] = 0.f;

    load_chunk(0);
    CP_COMMIT();

    for (int c = 0; c < n_chunks; c++) {
        CP_WAIT0();
        __syncthreads();
        if (c + 1 < n_chunks) load_chunk(c + 1);
        CP_COMMIT();

        const int buf = c & 1;
        const uint32_t aH = smu + SM_A + (uint32_t)(buf * TILE_B);
        const uint32_t aL = aH + 2u * TILE_B;
        const uint32_t bH = smu + SM_B + (uint32_t)(buf * TILE_B);
        const uint32_t bL = bH + 2u * TILE_B;

#pragma unroll
        for (int ks = 0; ks < 2; ks++) {
            const uint32_t kb = (uint32_t)(ks * 32);
            uint32_t ah[2][4], al[2][4];
            ldsm4(ah[0], aH + offA + kb);
            ldsm4(ah[1], aH + offA + 1280u + kb);
            ldsm4(al[0], aL + offA + kb);
            ldsm4(al[1], aL + offA + 1280u + kb);
#pragma unroll
            for (int g = 0; g < 2; g++) {
                const uint32_t go = (uint32_t)(g * 2560);
                uint32_t bh[4][2], bl[4][2];
                ldsm4(&bh[0][0], bH + offB + go + kb);
                ldsm4(&bh[2][0], bH + offB + go + 1280u + kb);
                ldsm4(&bl[0][0], bL + offB + go + kb);
                ldsm4(&bl[2][0], bL + offB + go + 1280u + kb);
#pragma unroll
                for (int mi = 0; mi < 2; mi++)
#pragma unroll
                    for (int q = 0; q < 4; q++) {
                        float* acq = acc[mi][g * 4 + q];
                        mma_bf16(acq, ah[mi], bh[q]);
                        mma_bf16(acq, ah[mi], bl[q]);
                        mma_bf16(acq, al[mi], bh[q]);
                    }
            }
        }
        __syncthreads();
    }

    // epilogue
#pragma unroll
    for (int mi = 0; mi < 2; mi++) {
        const int r0 = m0 + wm * 32 + mi * 16 + lr;
        const int r1 = r0 + 8;
        const float* dp0 = adds.direct ? adds.direct + (size_t)r0 * D : nullptr;
        const float* dp1 = adds.direct ? adds.direct + (size_t)r1 * D : nullptr;
        const float* gp[3][2];
#pragma unroll
        for (int t = 0; t < 3; t++) {
            if (adds.gat[t]) {
                gp[t][0] = adds.gat[t] + (size_t)__ldg(adds.gidx[t] + r0) * D;
                gp[t][1] = adds.gat[t] + (size_t)__ldg(adds.gidx[t] + r1) * D;
            } else {
                gp[t][0] = nullptr; gp[t][1] = nullptr;
            }
        }
        float *s00 = nullptr, *s01 = nullptr, *s10 = nullptr, *s11 = nullptr;
        if (scat.buf) {
            s00 = scat.buf + (size_t)__ldg(scat.i0 + r0) * D;
            s01 = scat.buf + (size_t)__ldg(scat.i0 + r1) * D;
            s10 = scat.buf + (size_t)__ldg(scat.i1 + r0) * D;
            s11 = scat.buf + (size_t)__ldg(scat.i1 + r1) * D;
        }
#pragma unroll
        for (int nj = 0; nj < 8; nj++) {
            const int col = n0 + wn * 64 + nj * 8 + lc * 2;
            float v0 = acc[mi][nj][0];
            float v1 = acc[mi][nj][1];
            float v2 = acc[mi][nj][2];
            float v3 = acc[mi][nj][3];
            if (dp0) {
                float2 t0 = *(const float2*)(dp0 + col);
                float2 t1 = *(const float2*)(dp1 + col);
                v0 += t0.x; v1 += t0.y; v2 += t1.x; v3 += t1.y;
            }
#pragma unroll
            for (int t = 0; t < 3; t++) {
                if (gp[t][0]) {
                    float2 t0 = *(const float2*)(gp[t][0] + col);
                    float2 t1 = *(const float2*)(gp[t][1] + col);
                    v0 += t0.x; v1 += t0.y; v2 += t1.x; v3 += t1.y;
                }
            }
            if (do_tanh) {
                v0 = tanhf(v0); v1 = tanhf(v1); v2 = tanhf(v2); v3 = tanhf(v3);
            }
            if (s00) {
                red2(s00 + col, v0, v1);
                red2(s10 + col, v0, v1);
                red2(s01 + col, v2, v3);
                red2(s11 + col, v2, v3);
            }
            if (out_f32) {
                *(float2*)(out_f32 + (size_t)r0 * D + col) = make_float2(v0, v1);
                *(float2*)(out_f32 + (size_t)r1 * D + col) = make_float2(v2, v3);
            }
            if (out_hi) {
                uint32_t h01, l01, h23, l23;
                split2(v0, v1, h01, l01);
                split2(v2, v3, h23, l23);
                const size_t o0 = (size_t)r0 * D + col;
                const size_t o1 = (size_t)r1 * D + col;
                *(uint32_t*)(out_hi + o0) = h01;  *(uint32_t*)(out_lo + o0) = l01;
                *(uint32_t*)(out_hi + o1) = h23;  *(uint32_t*)(out_lo + o1) = l23;
                if (out2_hi) {
                    *(uint32_t*)(out2_hi + o0) = h01;  *(uint32_t*)(out2_lo + o0) = l01;
                    *(uint32_t*)(out2_hi + o1) = h23;  *(uint32_t*)(out2_lo + o1) = l23;
                }
            }
        }
    }
}

// ---------------- small kernels ----------------
__global__ void k_offsets(const int* __restrict__ ids, int n, int* __restrict__ off)
{
    int m = blockIdx.x * blockDim.x + threadIdx.x;
    if (m > N_MOLS) return;
    int lo = 0, hi = n;
    while (lo < hi) {
        int mid = (lo + hi) >> 1;
        if (ids[mid] < m) lo = mid + 1; else hi = mid;
    }
    off[m] = lo;
}

__global__ void k_mol_mean(const float* __restrict__ atoms,
                           const int* __restrict__ aoff,
                           bf16* __restrict__ mhi, bf16* __restrict__ mlo)
{
    const int m = blockIdx.x, d = threadIdx.x;
    const int s = aoff[m], e = aoff[m + 1];
    float acc = 0.f;
    for (int i = s; i < e; i++) acc += atoms[(size_t)i * D_IN + d];
    float cnt = (float)(e - s);
    if (cnt < 1.f) cnt = 1.f;
    bf16 h, l;
    split1(acc / cnt, h, l);
    mhi[(size_t)m * D_IN + d] = h;
    mlo[(size_t)m * D_IN + d] = l;
}

__global__ void k_init_he0(const float* __restrict__ bo,
                           const float* __restrict__ Wfe,
                           bf16* __restrict__ e0hi, bf16* __restrict__ e0lo,
                           bf16* __restrict__ ehi,  bf16* __restrict__ elo)
{
    const int b = blockIdx.x, d = threadIdx.x * 2;
    const float o = bo[b];
    uint32_t h2, l2;
    split2(tanhf(o * Wfe[d]), tanhf(o * Wfe[d + 1]), h2, l2);
    const size_t off = (size_t)b * D + d;
    *(uint32_t*)(e0hi + off) = h2;  *(uint32_t*)(e0lo + off) = l2;
    *(uint32_t*)(ehi + off)  = h2;  *(uint32_t*)(elo + off)  = l2;
}

__global__ void k_segsum(const bf16* __restrict__ xhi, const bf16* __restrict__ xlo,
                         const int* __restrict__ off,
                         bf16* __restrict__ ohi, bf16* __restrict__ olo)
{
    const int m = blockIdx.x, d = threadIdx.x;
    const int s = off[m], e = off[m + 1];
    float acc = 0.f;
    for (int i = s; i < e; i++) {
        const size_t o = (size_t)i * D + d;
        acc += __bfloat162float(xhi[o]) + __bfloat162float(xlo[o]);
    }
    bf16 h, l;
    split1(acc, h, l);
    ohi[(size_t)m * D + d] = h;
    olo[(size_t)m * D + d] = l;
}

__global__ void k_f2p(const float* __restrict__ in,
                      bf16* __restrict__ hi, bf16* __restrict__ lo, int n2)
{
    int i = blockIdx.x * blockDim.x + threadIdx.x;
    if (i >= n2) return;
    float2 v = ((const float2*)in)[i];
    uint32_t h2, l2;
    split2(v.x, v.y, h2, l2);
    ((uint32_t*)hi)[i] = h2;
    ((uint32_t*)lo)[i] = l2;
}

__global__ void k_transpose_planes(const float* __restrict__ W,
                                   bf16* __restrict__ Thi, bf16* __restrict__ Tlo, int K)
{
    __shared__ float t[32][33];
    const int k0 = blockIdx.x * 32, nb = blockIdx.y * 32;
    const int tx = threadIdx.x, ty = threadIdx.y;
#pragma unroll
    for (int i = 0; i < 4; i++)
        t[ty + 8 * i][tx] = W[(size_t)(k0 + ty + 8 * i) * D + nb + tx];
    __syncthreads();
#pragma unroll
    for (int i = 0; i < 4; i++) {
        bf16 h, l;
        split1(t[tx][ty + 8 * i], h, l);
        const size_t o = (size_t)(nb + ty + 8 * i) * K + k0 + tx;
        Thi[o] = h;
        Tlo[o] = l;
    }
}

// ---------------- host orchestration ----------------
static bf16* sym_bf16(const void* sym) {
    void* p = nullptr;
    cudaGetSymbolAddress(&p, sym);
    return (bf16*)p;
}
static float* sym_f32(const void* sym) {
    void* p = nullptr;
    cudaGetSymbolAddress(&p, sym);
    return (float*)p;
}

extern "C" void kernel_launch(void* const* d_in, const int* in_sizes, int n_in,
                              void* d_out, int out_size)
{
    const float* atoms       = (const float*)d_in[0];
    const float* bond_orders = (const float*)d_in[1];
    const int*   bond_src    = (const int*)  d_in[2];
    const int*   bond_dst    = (const int*)  d_in[3];
    const int*   atom_mol    = (const int*)  d_in[4];
    const int*   bond_mol    = (const int*)  d_in[5];
    const float* W_fe        = (const float*)d_in[6];
    const float* W_fv        = (const float*)d_in[7];
    const float* W_fu        = (const float*)d_in[8];
    const float* W_e         = (const float*)d_in[9];
    const float* W_v         = (const float*)d_in[10];
    const float* W_u         = (const float*)d_in[11];

    bf16* he_hi  = sym_bf16(g_he_hi);   bf16* he_lo  = sym_bf16(g_he_lo);
    bf16* he0_hi = sym_bf16(g_he0_hi);  bf16* he0_lo = sym_bf16(g_he0_lo);
    bf16* hv_hi  = sym_bf16(g_hv_hi);   bf16* hv_lo  = sym_bf16(g_hv_lo);
    bf16* hv0_hi = sym_bf16(g_hv0_hi);  bf16* hv0_lo = sym_bf16(g_hv0_lo);
    bf16* ebv_hi = sym_bf16(g_ebv_hi);  bf16* ebv_lo = sym_bf16(g_ebv_lo);
    bf16* hu_hi  = sym_bf16(g_hu_hi);   bf16* hu_lo  = sym_bf16(g_hu_lo);
    bf16* hu0_hi = sym_bf16(g_hu0_hi);  bf16* hu0_lo = sym_bf16(g_hu0_lo);
    bf16* ebar_hi= sym_bf16(g_ebar_hi); bf16* ebar_lo= sym_bf16(g_ebar_lo);
    bf16* vbar_hi= sym_bf16(g_vbar_hi); bf16* vbar_lo= sym_bf16(g_vbar_lo);
    bf16* mm_hi  = sym_bf16(g_mm_hi);   bf16* mm_lo  = sym_bf16(g_mm_lo);
    bf16* at_hi  = sym_bf16(g_at_hi);   bf16* at_lo  = sym_bf16(g_at_lo);
    bf16* we_hi  = sym_bf16(g_we_hi);   bf16* we_lo  = sym_bf16(g_we_lo);
    bf16* wv_hi  = sym_bf16(g_wv_hi);   bf16* wv_lo  = sym_bf16(g_wv_lo);
    bf16* wu_hi  = sym_bf16(g_wu_hi);   bf16* wu_lo  = sym_bf16(g_wu_lo);
    bf16* wfv_hi = sym_bf16(g_wfv_hi);  bf16* wfv_lo = sym_bf16(g_wfv_lo);
    bf16* wfu_hi = sym_bf16(g_wfu_hi);  bf16* wfu_lo = sym_bf16(g_wfu_lo);
    float* ebv_f = sym_f32(g_ebv_f);
    float* E0    = sym_f32(g_E0);
    float* V0t   = sym_f32(g_V0t);
    float* Ue    = sym_f32(g_Ue);
    float* Uv    = sym_f32(g_Uv);
    float* Vs    = sym_f32(g_Vs);
    float* Vd    = sym_f32(g_Vd);
    int *boff, *aoff;
    { void* p; cudaGetSymbolAddress(&p, g_boff); boff = (int*)p; }
    { void* p; cudaGetSymbolAddress(&p, g_aoff); aoff = (int*)p; }

    const size_t SZ_E = (size_t)N_BONDS * D;
    const size_t SZ_V = (size_t)N_ATOMS * D;
    const size_t SZ_U = (size_t)N_MOLS * D;

    cudaFuncSetAttribute(k_mma, cudaFuncAttributeMaxDynamicSharedMemorySize, SMEM_BYTES);

    const Adds noadd = {};
    const Scat noscat = {};

    const int offBlocks = (N_MOLS + 1 + 255) / 256;
    k_offsets<<<offBlocks, 256>>>(bond_mol, N_BONDS, boff);
    k_offsets<<<offBlocks, 256>>>(atom_mol, N_ATOMS, aoff);

    k_transpose_planes<<<dim3(5 * D / 32, 8), dim3(32, 8)>>>(W_e,  we_hi,  we_lo,  5 * D);
    k_transpose_planes<<<dim3(4 * D / 32, 8), dim3(32, 8)>>>(W_v,  wv_hi,  wv_lo,  4 * D);
    k_transpose_planes<<<dim3(4 * D / 32, 8), dim3(32, 8)>>>(W_u,  wu_hi,  wu_lo,  4 * D);
    k_transpose_planes<<<dim3(D_IN / 32, 8),  dim3(32, 8)>>>(W_fv, wfv_hi, wfv_lo, D_IN);
    k_transpose_planes<<<dim3(D_IN / 32, 8),  dim3(32, 8)>>>(W_fu, wfu_hi, wfu_lo, D_IN);

    k_f2p<<<(int)((N_ATOMS * (size_t)D_IN / 2 + 255) / 256), 256>>>(atoms, at_hi, at_lo,
                                                                    N_ATOMS * D_IN / 2);
    k_init_he0<<<N_BONDS, 128>>>(bond_orders, W_fe, he0_hi, he0_lo, he_hi, he_lo);
    k_mol_mean<<<N_MOLS, 128>>>(atoms, aoff, mm_hi, mm_lo);

    // h_v0 = tanh(atoms @ W_fv); seed h_v
    {
        Srcs s = {};
        s.Ahi[0] = at_hi; s.Alo[0] = at_lo; s.wblk[0] = 0;
        k_mma<<<dim3(2, N_ATOMS / 128), 256, SMEM_BYTES>>>(
            s, D_IN, 2, 4, wfv_hi, wfv_lo, D_IN, noadd, noscat, 1,
            nullptr, hv0_hi, hv0_lo, hv_hi, hv_lo);
    }
    // h_u0 = tanh(mol_mean @ W_fu); seed h_u
    {
        Srcs s = {};
        s.Ahi[0] = mm_hi; s.Alo[0] = mm_lo; s.wblk[0] = 0;
        k_mma<<<dim3(2, N_MOLS / 128), 256, SMEM_BYTES>>>(
            s, D_IN, 2, 4, wfu_hi, wfu_lo, D_IN, noadd, noscat, 1,
            nullptr, hu0_hi, hu0_lo, hu_hi, hu_lo);
    }
    // E0 = he0 @ We[256:512]
    {
        Srcs s = {};
        s.Ahi[0] = he0_hi; s.Alo[0] = he0_lo; s.wblk[0] = 1;
        k_mma<<<dim3(2, N_BONDS / 128), 256, SMEM_BYTES>>>(
            s, D, 3, 8, we_hi, we_lo, 5 * D, noadd, noscat, 0,
            E0, nullptr, nullptr, nullptr, nullptr);
    }
    // V0t = hv0 @ Wv[256:512]
    {
        Srcs s = {};
        s.Ahi[0] = hv0_hi; s.Alo[0] = hv0_lo; s.wblk[0] = 1;
        k_mma<<<dim3(2, N_ATOMS / 128), 256, SMEM_BYTES>>>(
            s, D, 3, 8, wv_hi, wv_lo, 4 * D, noadd, noscat, 0,
            V0t, nullptr, nullptr, nullptr, nullptr);
    }

    int ec = 0, vc = 0, uc = 0;

    for (int it = 0; it < 3; it++) {
        // Ue = hu @ We[1024:1280]
        {
            Srcs s = {};
            s.Ahi[0] = hu_hi + (size_t)uc * SZ_U; s.Alo[0] = hu_lo + (size_t)uc * SZ_U;
            s.wblk[0] = 4;
            k_mma<<<dim3(2, N_MOLS / 128), 256, SMEM_BYTES>>>(
                s, D, 3, 8, we_hi, we_lo, 5 * D, noadd, noscat, 0,
                Ue, nullptr, nullptr, nullptr, nullptr);
        }
        // Vs = hv @ We[512:768] ; Vd = hv @ We[768:1024]  (per-atom)
        {
            Srcs s = {};
            s.Ahi[0] = hv_hi + (size_t)vc * SZ_V; s.Alo[0] = hv_lo + (size_t)vc * SZ_V;
            s.wblk[0] = 2;
            k_mma<<<dim3(2, N_ATOMS / 128), 256, SMEM_BYTES>>>(
                s, D, 3, 8, we_hi, we_lo, 5 * D, noadd, noscat, 0,
                Vs, nullptr, nullptr, nullptr, nullptr);
            s.wblk[0] = 3;
            k_mma<<<dim3(2, N_ATOMS / 128), 256, SMEM_BYTES>>>(
                s, D, 3, 8, we_hi, we_lo, 5 * D, noadd, noscat, 0,
                Vd, nullptr, nullptr, nullptr, nullptr);
        }
        if (it < 2)
            cudaMemsetAsync(ebv_f, 0, SZ_V * sizeof(float), 0);

        // edge update: single GEMM source (he); adds E0 + Ue[bond_mol] + Vs[src] + Vd[dst];
        // scatters tanh result into ebv (except final iter)
        {
            Srcs s = {};
            s.Ahi[0] = he_hi + (size_t)ec * SZ_E;  s.Alo[0] = he_lo + (size_t)ec * SZ_E;
            s.wblk[0] = 0;
            Adds a = {};
            a.direct = E0;
            a.gat[0] = Ue; a.gidx[0] = bond_mol;
            a.gat[1] = Vs; a.gidx[1] = bond_src;
            a.gat[2] = Vd; a.gidx[2] = bond_dst;
            if (it == 2) {
                k_mma<<<dim3(2, N_BONDS / 128), 256, SMEM_BYTES>>>(
                    s, D, 3, 8, we_hi, we_lo, 5 * D, a, noscat, 1,
                    (float*)d_out, nullptr, nullptr, nullptr, nullptr);
                break;
            }
            Scat sc = {ebv_f, bond_src, bond_dst};
            const int en = ec ^ 1;
            k_mma<<<dim3(2, N_BONDS / 128), 256, SMEM_BYTES>>>(
                s, D, 3, 8, we_hi, we_lo, 5 * D, a, sc, 1,
                nullptr, he_hi + (size_t)en * SZ_E, he_lo + (size_t)en * SZ_E,
                nullptr, nullptr);
            ec = en;
        }

        k_f2p<<<(int)((SZ_V / 2 + 255) / 256), 256>>>(ebv_f, ebv_hi, ebv_lo, (int)(SZ_V / 2));

        // Uv = hu @ Wv[768:1024]
        {
            Srcs s = {};
            s.Ahi[0] = hu_hi + (size_t)uc * SZ_U; s.Alo[0] = hu_lo + (size_t)uc * SZ_U;
            s.wblk[0] = 3;
            k_mma<<<dim3(2, N_MOLS / 128), 256, SMEM_BYTES>>>(
                s, D, 3, 8, wv_hi, wv_lo, 4 * D, noadd, noscat, 0,
                Uv, nullptr, nullptr, nullptr, nullptr);
        }
        // node update: srcs hv + ebv; adds V0t + Uv[atom_mol]
        {
            Srcs s = {};
            s.Ahi[0] = hv_hi + (size_t)vc * SZ_V;  s.Alo[0] = hv_lo + (size_t)vc * SZ_V;
            s.wblk[0] = 0;
            s.Ahi[1] = ebv_hi;                      s.Alo[1] = ebv_lo;
            s.wblk[1] = 2;
            Adds a = {};
            a.direct = V0t;
            a.gat[0] = Uv; a.gidx[0] = atom_mol;
            const int vn = vc ^ 1;
            k_mma<<<dim3(2, N_ATOMS / 128), 256, SMEM_BYTES>>>(
                s, D, 3, 16, wv_hi, wv_lo, 4 * D, a, noscat, 1,
                nullptr, hv_hi + (size_t)vn * SZ_V, hv_lo + (size_t)vn * SZ_V,
                nullptr, nullptr);
            vc = vn;
        }

        k_segsum<<<N_MOLS, 256>>>(he_hi + (size_t)ec * SZ_E, he_lo + (size_t)ec * SZ_E,
                                  boff, ebar_hi, ebar_lo);
        k_segsum<<<N_MOLS, 256>>>(hv_hi + (size_t)vc * SZ_V, hv_lo + (size_t)vc * SZ_V,
                                  aoff, vbar_hi, vbar_lo);

        // global update
        {
            Srcs s = {};
            s.Ahi[0] = hu_hi + (size_t)uc * SZ_U;  s.Alo[0] = hu_lo + (size_t)uc * SZ_U;
            s.wblk[0] = 0;
            s.Ahi[1] = hu0_hi;                      s.Alo[1] = hu0_lo;
            s.wblk[1] = 1;
            s.Ahi[2] = ebar_hi;                     s.Alo[2] = ebar_lo;
            s.wblk[2] = 2;
            s.Ahi[3] = vbar_hi;                     s.Alo[3] = vbar_lo;
            s.wblk[3] = 3;
            const int un = uc ^ 1;
            k_mma<<<dim3(2, N_MOLS / 128), 256, SMEM_BYTES>>>(
                s, D, 3, 32, wu_hi, wu_lo, 4 * D, noadd, noscat, 1,
                nullptr, hu_hi + (size_t)un * SZ_U, hu_lo + (size_t)un * SZ_U,
                nullptr, nullptr);
            uc = un;
        }
    }
}

// round 8
// speedup vs baseline: 2.2582x; 1.0646x over previous
#include <cuda_runtime.h>
#include <cuda_bf16.h>
#include <math.h>
#include <stdint.h>

typedef __nv_bfloat16 bf16;

#define N_ATOMS 65536
#define N_BONDS 98304
#define N_MOLS  4096
#define D_IN    128
#define D       256

// ---------------- scratch (device globals; no allocation allowed) ----------------
__device__ bf16 g_he_hi [2][(size_t)N_BONDS * D];
__device__ bf16 g_he_lo [2][(size_t)N_BONDS * D];
__device__ bf16 g_he0_hi[(size_t)N_BONDS * D];
__device__ bf16 g_he0_lo[(size_t)N_BONDS * D];
__device__ bf16 g_hv_hi [2][(size_t)N_ATOMS * D];
__device__ bf16 g_hv_lo [2][(size_t)N_ATOMS * D];
__device__ bf16 g_hv0_hi[(size_t)N_ATOMS * D];
__device__ bf16 g_hv0_lo[(size_t)N_ATOMS * D];
__device__ float g_ebv_f [(size_t)N_ATOMS * D];
__device__ bf16 g_hu_hi [2][(size_t)N_MOLS * D];
__device__ bf16 g_hu_lo [2][(size_t)N_MOLS * D];
__device__ bf16 g_hu0_hi[(size_t)N_MOLS * D];
__device__ bf16 g_hu0_lo[(size_t)N_MOLS * D];
__device__ bf16 g_ebar_hi[(size_t)N_MOLS * D];
__device__ bf16 g_ebar_lo[(size_t)N_MOLS * D];
__device__ bf16 g_vbar_hi[(size_t)N_MOLS * D];
__device__ bf16 g_vbar_lo[(size_t)N_MOLS * D];
__device__ bf16 g_mm_hi [(size_t)N_MOLS * D_IN];
__device__ bf16 g_mm_lo [(size_t)N_MOLS * D_IN];
__device__ bf16 g_at_hi [(size_t)N_ATOMS * D_IN];
__device__ bf16 g_at_lo [(size_t)N_ATOMS * D_IN];
__device__ bf16 g_we_hi [(size_t)D * 5 * D];
__device__ bf16 g_we_lo [(size_t)D * 5 * D];
__device__ bf16 g_wv_hi [(size_t)D * 4 * D];
__device__ bf16 g_wv_lo [(size_t)D * 4 * D];
__device__ bf16 g_wu_hi [(size_t)D * 4 * D];
__device__ bf16 g_wu_lo [(size_t)D * 4 * D];
__device__ bf16 g_wfv_hi[(size_t)D * D_IN];
__device__ bf16 g_wfv_lo[(size_t)D * D_IN];
__device__ bf16 g_wfu_hi[(size_t)D * D_IN];
__device__ bf16 g_wfu_lo[(size_t)D * D_IN];
// precomputed fp32 epilogue-add terms
__device__ float g_E0 [(size_t)N_BONDS * D];   // he0 @ We[256:512]
__device__ float g_V0t[(size_t)N_ATOMS * D];   // hv0 @ Wv[256:512]
__device__ float g_U0 [(size_t)N_MOLS * D];    // hu0 @ Wu[256:512]
__device__ float g_Ue [(size_t)N_MOLS * D];    // hu  @ We[1024:1280]
__device__ float g_Uv [(size_t)N_MOLS * D];    // hu  @ Wv[768:1024]
__device__ float g_Vs [(size_t)N_ATOMS * D];   // hv  @ We[512:768]
__device__ float g_Vd [(size_t)N_ATOMS * D];   // hv  @ We[768:1024]
__device__ int  g_boff[N_MOLS + 1];
__device__ int  g_aoff[N_MOLS + 1];

// ---------------- helpers ----------------
__device__ __forceinline__ uint32_t smem_u32(const void* p) {
    uint32_t a;
    asm("{ .reg .u64 t; cvta.to.shared.u64 t, %1; cvt.u32.u64 %0, t; }" : "=r"(a) : "l"(p));
    return a;
}
__device__ __forceinline__ void cp16(uint32_t dst, const void* src) {
    asm volatile("cp.async.cg.shared.global [%0], [%1], 16;" :: "r"(dst), "l"(src) : "memory");
}
#define CP_COMMIT()  asm volatile("cp.async.commit_group;" ::: "memory")
#define CP_WAIT0()   asm volatile("cp.async.wait_group 0;" ::: "memory")

__device__ __forceinline__ void ldsm4(uint32_t* r, uint32_t addr) {
    asm volatile("ldmatrix.sync.aligned.m8n8.x4.shared.b16 {%0,%1,%2,%3}, [%4];"
        : "=r"(r[0]), "=r"(r[1]), "=r"(r[2]), "=r"(r[3]) : "r"(addr));
}
__device__ __forceinline__ void mma_bf16(float* c, const uint32_t* a, const uint32_t* b) {
    asm volatile(
        "mma.sync.aligned.m16n8k16.row.col.f32.bf16.bf16.f32 "
        "{%0,%1,%2,%3}, {%4,%5,%6,%7}, {%8,%9}, {%0,%1,%2,%3};"
        : "+f"(c[0]), "+f"(c[1]), "+f"(c[2]), "+f"(c[3])
        : "r"(a[0]), "r"(a[1]), "r"(a[2]), "r"(a[3]), "r"(b[0]), "r"(b[1]));
}
__device__ __forceinline__ void red2(float* p, float a, float b) {
    asm volatile("red.global.add.v2.f32 [%0], {%1,%2};"
        :: "l"(p), "f"(a), "f"(b) : "memory");
}
__device__ __forceinline__ void split1(float v, bf16& h, bf16& l) {
    h = __float2bfloat16(v);
    l = __float2bfloat16(v - __bfloat162float(h));
}
__device__ __forceinline__ void split2(float v0, float v1, uint32_t& h2, uint32_t& l2) {
    bf16 h0, l0, h1, l1;
    split1(v0, h0, l0);
    split1(v1, h1, l1);
    h2 = (uint32_t)__bfloat16_as_ushort(h0) | ((uint32_t)__bfloat16_as_ushort(h1) << 16);
    l2 = (uint32_t)__bfloat16_as_ushort(l0) | ((uint32_t)__bfloat16_as_ushort(l1) << 16);
}

// ---------------- fused multi-source bf16x3 GEMM (+adds, +scatter, +tanh) ---------
struct Srcs {
    const void* Ahi[4];   // bf16 hi-plane OR fp32 buffer (isf32)
    const void* Alo[4];
    const int*  idx[4];
    int         wblk[4];
    int         isf32[4];
};
struct Adds {
    const float* direct;
    const float* gat[3];
    const int*   gidx[3];
};
struct Scat {
    float*     buf;
    const int* i0;
    const int* i1;
};

#define TILE_B   10240
#define SM_A     0
#define SM_B     40960
#define SMEM_BYTES 81920

__global__ void __launch_bounds__(256, 2)
k_mma(Srcs srcs, int ksrc, int cshift, int n_chunks,
      const bf16* __restrict__ Whi, const bf16* __restrict__ Wlo, int kstride,
      Adds adds, Scat scat, int do_tanh,
      int ysplit, int wblk_alt,
      float* __restrict__ out_f32, float* __restrict__ out_alt,
      bf16* __restrict__ out_hi, bf16* __restrict__ out_lo,
      bf16* __restrict__ out2_hi, bf16* __restrict__ out2_lo)
{
    extern __shared__ char smc[];
    const uint32_t smu = smem_u32(smc);

    const int tid  = threadIdx.x;
    const int lane = tid & 31;
    const int w    = tid >> 5;
    const int wm   = w & 3;
    const int wn   = w >> 2;
    const int lr   = lane >> 2;
    const int lc   = lane & 3;

    const int n0 = blockIdx.x * 128;
    const int yb = blockIdx.y;
    const bool alt = (ysplit > 0) && (yb >= ysplit);
    const int m0 = (alt ? yb - ysplit : yb) * 128;

    const int cmask = (ksrc >> 5) - 1;

    const int r8 = lane & 7, j8 = lane >> 3;
    const uint32_t offA = (uint32_t)((r8 + (j8 & 1) * 8) * 80 + ((j8 >> 1) & 1) * 16)
                        + (uint32_t)(wm * 32) * 80u;
    const uint32_t offB = (uint32_t)(r8 * 80 + ((j8 >> 1) & 1) * 640 + (j8 & 1) * 16)
                        + (uint32_t)(wn * 64) * 80u;

    const int arow = tid >> 1;
    const int apl  = tid & 1;
    int cur_s = -1, is32 = 0, wcur = 0;
    const bf16*  aptr = nullptr;
    const float* a32  = nullptr;
    const bf16* wbase = apl ? Wlo : Whi;

    auto load_chunk = [&](int c) {
        const int buf = c & 1;
        const int s = c >> cshift;
        if (s != cur_s) {
            cur_s = s;
            is32 = srcs.isf32[s];
            int gr = m0 + arow;
            const int* ix = srcs.idx[s];
            if (ix) gr = __ldg(ix + gr);
            if (is32) a32 = (const float*)srcs.Ahi[s] + (size_t)gr * ksrc;
            else aptr = (const bf16*)(apl ? srcs.Alo[s] : srcs.Ahi[s]) + (size_t)gr * ksrc;
            wcur = (s == 0 && alt) ? wblk_alt : srcs.wblk[s];
        }
        const uint32_t ad = smu + (uint32_t)(SM_A + apl * 2 * TILE_B + buf * TILE_B + arow * 80);
        if (is32) {
            const float* fs = a32 + ((c & cmask) << 5);
#pragma unroll
            for (int i = 0; i < 4; i++) {
                float4 x = __ldg((const float4*)(fs + i * 8));
                float4 y = __ldg((const float4*)(fs + i * 8 + 4));
                uint32_t h, l, r0, r1, r2, r3;
                split2(x.x, x.y, h, l); r0 = apl ? l : h;
                split2(x.z, x.w, h, l); r1 = apl ? l : h;
                split2(y.x, y.y, h, l); r2 = apl ? l : h;
                split2(y.z, y.w, h, l); r3 = apl ? l : h;
                asm volatile("st.shared.v4.b32 [%0], {%1,%2,%3,%4};"
                    :: "r"(ad + (uint32_t)(i * 16)), "r"(r0), "r"(r1), "r"(r2), "r"(r3)
                    : "memory");
            }
        } else {
            const bf16* as = aptr + ((c & cmask) << 5);
            cp16(ad,      as);
            cp16(ad + 16, as + 8);
            cp16(ad + 32, as + 16);
            cp16(ad + 48, as + 24);
        }
        const bf16* bs = wbase + (size_t)(n0 + arow) * kstride
                       + (wcur << 8) + ((c & cmask) << 5);
        const uint32_t bd = smu + (uint32_t)(SM_B + apl * 2 * TILE_B + buf * TILE_B + arow * 80);
        cp16(bd,      bs);
        cp16(bd + 16, bs + 8);
        cp16(bd + 32, bs + 16);
        cp16(bd + 48, bs + 24);
    };

    float acc[2][8][4];
#pragma unroll
    for (int mi = 0; mi < 2; mi++)
#pragma unroll
        for (int nj = 0; nj < 8; nj++)
#pragma unroll
            for (int q = 0; q < 4; q++) acc[mi][nj][q] = 0.f;

    load_chunk(0);
    CP_COMMIT();

    for (int c = 0; c < n_chunks; c++) {
        CP_WAIT0();
        __syncthreads();
        if (c + 1 < n_chunks) load_chunk(c + 1);
        CP_COMMIT();

        const int buf = c & 1;
        const uint32_t aH = smu + SM_A + (uint32_t)(buf * TILE_B);
        const uint32_t aL = aH + 2u * TILE_B;
        const uint32_t bH = smu + SM_B + (uint32_t)(buf * TILE_B);
        const uint32_t bL = bH + 2u * TILE_B;

#pragma unroll
        for (int ks = 0; ks < 2; ks++) {
            const uint32_t kb = (uint32_t)(ks * 32);
            uint32_t ah[2][4], al[2][4];
            ldsm4(ah[0], aH + offA + kb);
            ldsm4(ah[1], aH + offA + 1280u + kb);
            ldsm4(al[0], aL + offA + kb);
            ldsm4(al[1], aL + offA + 1280u + kb);
#pragma unroll
            for (int g = 0; g < 2; g++) {
                const uint32_t go = (uint32_t)(g * 2560);
                uint32_t bh[4][2], bl[4][2];
                ldsm4(&bh[0][0], bH + offB + go + kb);
                ldsm4(&bh[2][0], bH + offB + go + 1280u + kb);
                ldsm4(&bl[0][0], bL + offB + go + kb);
                ldsm4(&bl[2][0], bL + offB + go + 1280u + kb);
#pragma unroll
                for (int mi = 0; mi < 2; mi++)
#pragma unroll
                    for (int q = 0; q < 4; q++) {
                        float* acq = acc[mi][g * 4 + q];
                        mma_bf16(acq, ah[mi], bh[q]);
                        mma_bf16(acq, ah[mi], bl[q]);
                        mma_bf16(acq, al[mi], bh[q]);
                    }
            }
        }
        __syncthreads();
    }

    float* outf = alt ? out_alt : out_f32;

    // epilogue
#pragma unroll
    for (int mi = 0; mi < 2; mi++) {
        const int r0 = m0 + wm * 32 + mi * 16 + lr;
        const int r1 = r0 + 8;
        const float* dp0 = adds.direct ? adds.direct + (size_t)r0 * D : nullptr;
        const float* dp1 = adds.direct ? adds.direct + (size_t)r1 * D : nullptr;
        const float* gp[3][2];
#pragma unroll
        for (int t = 0; t < 3; t++) {
            if (adds.gat[t]) {
                gp[t][0] = adds.gat[t] + (size_t)__ldg(adds.gidx[t] + r0) * D;
                gp[t][1] = adds.gat[t] + (size_t)__ldg(adds.gidx[t] + r1) * D;
            } else {
                gp[t][0] = nullptr; gp[t][1] = nullptr;
            }
        }
        float *s00 = nullptr, *s01 = nullptr, *s10 = nullptr, *s11 = nullptr;
        if (scat.buf) {
            s00 = scat.buf + (size_t)__ldg(scat.i0 + r0) * D;
            s01 = scat.buf + (size_t)__ldg(scat.i0 + r1) * D;
            s10 = scat.buf + (size_t)__ldg(scat.i1 + r0) * D;
            s11 = scat.buf + (size_t)__ldg(scat.i1 + r1) * D;
        }
#pragma unroll
        for (int nj = 0; nj < 8; nj++) {
            const int col = n0 + wn * 64 + nj * 8 + lc * 2;
            float v0 = acc[mi][nj][0];
            float v1 = acc[mi][nj][1];
            float v2 = acc[mi][nj][2];
            float v3 = acc[mi][nj][3];
            if (dp0) {
                float2 t0 = *(const float2*)(dp0 + col);
                float2 t1 = *(const float2*)(dp1 + col);
                v0 += t0.x; v1 += t0.y; v2 += t1.x; v3 += t1.y;
            }
#pragma unroll
            for (int t = 0; t < 3; t++) {
                if (gp[t][0]) {
                    float2 t0 = *(const float2*)(gp[t][0] + col);
                    float2 t1 = *(const float2*)(gp[t][1] + col);
                    v0 += t0.x; v1 += t0.y; v2 += t1.x; v3 += t1.y;
                }
            }
            if (do_tanh) {
                v0 = tanhf(v0); v1 = tanhf(v1); v2 = tanhf(v2); v3 = tanhf(v3);
            }
            if (s00) {
                red2(s00 + col, v0, v1);
                red2(s10 + col, v0, v1);
                red2(s01 + col, v2, v3);
                red2(s11 + col, v2, v3);
            }
            if (outf) {
                *(float2*)(outf + (size_t)r0 * D + col) = make_float2(v0, v1);
                *(float2*)(outf + (size_t)r1 * D + col) = make_float2(v2, v3);
            }
            if (out_hi) {
                uint32_t h01, l01, h23, l23;
                split2(v0, v1, h01, l01);
                split2(v2, v3, h23, l23);
                const size_t o0 = (size_t)r0 * D + col;
                const size_t o1 = (size_t)r1 * D + col;
                *(uint32_t*)(out_hi + o0) = h01;  *(uint32_t*)(out_lo + o0) = l01;
                *(uint32_t*)(out_hi + o1) = h23;  *(uint32_t*)(out_lo + o1) = l23;
                if (out2_hi) {
                    *(uint32_t*)(out2_hi + o0) = h01;  *(uint32_t*)(out2_lo + o0) = l01;
                    *(uint32_t*)(out2_hi + o1) = h23;  *(uint32_t*)(out2_lo + o1) = l23;
                }
            }
        }
    }
}

// ---------------- small kernels ----------------
__global__ void k_offsets(const int* __restrict__ ids, int n, int* __restrict__ off)
{
    int m = blockIdx.x * blockDim.x + threadIdx.x;
    if (m > N_MOLS) return;
    int lo = 0, hi = n;
    while (lo < hi) {
        int mid = (lo + hi) >> 1;
        if (ids[mid] < m) lo = mid + 1; else hi = mid;
    }
    off[m] = lo;
}

__global__ void k_mol_mean(const float* __restrict__ atoms,
                           const int* __restrict__ aoff,
                           bf16* __restrict__ mhi, bf16* __restrict__ mlo)
{
    const int m = blockIdx.x, d = threadIdx.x;
    const int s = aoff[m], e = aoff[m + 1];
    float acc = 0.f;
    for (int i = s; i < e; i++) acc += atoms[(size_t)i * D_IN + d];
    float cnt = (float)(e - s);
    if (cnt < 1.f) cnt = 1.f;
    bf16 h, l;
    split1(acc / cnt, h, l);
    mhi[(size_t)m * D_IN + d] = h;
    mlo[(size_t)m * D_IN + d] = l;
}

__global__ void k_init_he0(const float* __restrict__ bo,
                           const float* __restrict__ Wfe,
                           bf16* __restrict__ e0hi, bf16* __restrict__ e0lo,
                           bf16* __restrict__ ehi,  bf16* __restrict__ elo)
{
    const int b = blockIdx.x, d = threadIdx.x * 2;
    const float o = bo[b];
    uint32_t h2, l2;
    split2(tanhf(o * Wfe[d]), tanhf(o * Wfe[d + 1]), h2, l2);
    const size_t off = (size_t)b * D + d;
    *(uint32_t*)(e0hi + off) = h2;  *(uint32_t*)(e0lo + off) = l2;
    *(uint32_t*)(ehi + off)  = h2;  *(uint32_t*)(elo + off)  = l2;
}

// merged pair of segment sums (blockIdx.y selects edge/node set)
__global__ void k_segsum2(const bf16* __restrict__ xhi0, const bf16* __restrict__ xlo0,
                          const int* __restrict__ off0,
                          bf16* __restrict__ ohi0, bf16* __restrict__ olo0,
                          const bf16* __restrict__ xhi1, const bf16* __restrict__ xlo1,
                          const int* __restrict__ off1,
                          bf16* __restrict__ ohi1, bf16* __restrict__ olo1)
{
    const int m = blockIdx.x, d = threadIdx.x;
    const bf16* xhi; const bf16* xlo; const int* off; bf16* ohi; bf16* olo;
    if (blockIdx.y == 0) { xhi = xhi0; xlo = xlo0; off = off0; ohi = ohi0; olo = olo0; }
    else                 { xhi = xhi1; xlo = xlo1; off = off1; ohi = ohi1; olo = olo1; }
    const int s = off[m], e = off[m + 1];
    float acc = 0.f;
    for (int i = s; i < e; i++) {
        const size_t o = (size_t)i * D + d;
        acc += __bfloat162float(xhi[o]) + __bfloat162float(xlo[o]);
    }
    bf16 h, l;
    split1(acc, h, l);
    ohi[(size_t)m * D + d] = h;
    olo[(size_t)m * D + d] = l;
}

__global__ void k_f2p(const float* __restrict__ in,
                      bf16* __restrict__ hi, bf16* __restrict__ lo, int n2)
{
    int i = blockIdx.x * blockDim.x + threadIdx.x;
    if (i >= n2) return;
    float2 v = ((const float2*)in)[i];
    uint32_t h2, l2;
    split2(v.x, v.y, h2, l2);
    ((uint32_t*)hi)[i] = h2;
    ((uint32_t*)lo)[i] = l2;
}

__global__ void k_transpose_planes(const float* __restrict__ W,
                                   bf16* __restrict__ Thi, bf16* __restrict__ Tlo, int K)
{
    __shared__ float t[32][33];
    const int k0 = blockIdx.x * 32, nb = blockIdx.y * 32;
    const int tx = threadIdx.x, ty = threadIdx.y;
#pragma unroll
    for (int i = 0; i < 4; i++)
        t[ty + 8 * i][tx] = W[(size_t)(k0 + ty + 8 * i) * D + nb + tx];
    __syncthreads();
#pragma unroll
    for (int i = 0; i < 4; i++) {
        bf16 h, l;
        split1(t[tx][ty + 8 * i], h, l);
        const size_t o = (size_t)(nb + ty + 8 * i) * K + k0 + tx;
        Thi[o] = h;
        Tlo[o] = l;
    }
}

// ---------------- host orchestration ----------------
static bf16* sym_bf16(const void* sym) {
    void* p = nullptr;
    cudaGetSymbolAddress(&p, sym);
    return (bf16*)p;
}
static float* sym_f32(const void* sym) {
    void* p = nullptr;
    cudaGetSymbolAddress(&p, sym);
    return (float*)p;
}

extern "C" void kernel_launch(void* const* d_in, const int* in_sizes, int n_in,
                              void* d_out, int out_size)
{
    const float* atoms       = (const float*)d_in[0];
    const float* bond_orders = (const float*)d_in[1];
    const int*   bond_src    = (const int*)  d_in[2];
    const int*   bond_dst    = (const int*)  d_in[3];
    const int*   atom_mol    = (const int*)  d_in[4];
    const int*   bond_mol    = (const int*)  d_in[5];
    const float* W_fe        = (const float*)d_in[6];
    const float* W_fv        = (const float*)d_in[7];
    const float* W_fu        = (const float*)d_in[8];
    const float* W_e         = (const float*)d_in[9];
    const float* W_v         = (const float*)d_in[10];
    const float* W_u         = (const float*)d_in[11];

    bf16* he_hi  = sym_bf16(g_he_hi);   bf16* he_lo  = sym_bf16(g_he_lo);
    bf16* he0_hi = sym_bf16(g_he0_hi);  bf16* he0_lo = sym_bf16(g_he0_lo);
    bf16* hv_hi  = sym_bf16(g_hv_hi);   bf16* hv_lo  = sym_bf16(g_hv_lo);
    bf16* hv0_hi = sym_bf16(g_hv0_hi);  bf16* hv0_lo = sym_bf16(g_hv0_lo);
    bf16* hu_hi  = sym_bf16(g_hu_hi);   bf16* hu_lo  = sym_bf16(g_hu_lo);
    bf16* hu0_hi = sym_bf16(g_hu0_hi);  bf16* hu0_lo = sym_bf16(g_hu0_lo);
    bf16* ebar_hi= sym_bf16(g_ebar_hi); bf16* ebar_lo= sym_bf16(g_ebar_lo);
    bf16* vbar_hi= sym_bf16(g_vbar_hi); bf16* vbar_lo= sym_bf16(g_vbar_lo);
    bf16* mm_hi  = sym_bf16(g_mm_hi);   bf16* mm_lo  = sym_bf16(g_mm_lo);
    bf16* at_hi  = sym_bf16(g_at_hi);   bf16* at_lo  = sym_bf16(g_at_lo);
    bf16* we_hi  = sym_bf16(g_we_hi);   bf16* we_lo  = sym_bf16(g_we_lo);
    bf16* wv_hi  = sym_bf16(g_wv_hi);   bf16* wv_lo  = sym_bf16(g_wv_lo);
    bf16* wu_hi  = sym_bf16(g_wu_hi);   bf16* wu_lo  = sym_bf16(g_wu_lo);
    bf16* wfv_hi = sym_bf16(g_wfv_hi);  bf16* wfv_lo = sym_bf16(g_wfv_lo);
    bf16* wfu_hi = sym_bf16(g_wfu_hi);  bf16* wfu_lo = sym_bf16(g_wfu_lo);
    float* ebv_f = sym_f32(g_ebv_f);
    float* E0    = sym_f32(g_E0);
    float* V0t   = sym_f32(g_V0t);
    float* U0    = sym_f32(g_U0);
    float* Ue    = sym_f32(g_Ue);
    float* Uv    = sym_f32(g_Uv);
    float* Vs    = sym_f32(g_Vs);
    float* Vd    = sym_f32(g_Vd);
    int *boff, *aoff;
    { void* p; cudaGetSymbolAddress(&p, g_boff); boff = (int*)p; }
    { void* p; cudaGetSymbolAddress(&p, g_aoff); aoff = (int*)p; }

    const size_t SZ_E = (size_t)N_BONDS * D;
    const size_t SZ_V = (size_t)N_ATOMS * D;
    const size_t SZ_U = (size_t)N_MOLS * D;

    cudaFuncSetAttribute(k_mma, cudaFuncAttributeMaxDynamicSharedMemorySize, SMEM_BYTES);

    // lazily created side stream + events (host resources only; device work identical per call)
    static cudaStream_t s1 = nullptr;
    static cudaEvent_t evs[8];
    if (!s1) {
        cudaStreamCreateWithFlags(&s1, cudaStreamNonBlocking);
        for (int i = 0; i < 8; i++) cudaEventCreateWithFlags(&evs[i], cudaEventDisableTiming);
    }

    const Adds noadd = {};
    const Scat noscat = {};

    const int offBlocks = (N_MOLS + 1 + 255) / 256;
    k_offsets<<<offBlocks, 256>>>(bond_mol, N_BONDS, boff);
    k_offsets<<<offBlocks, 256>>>(atom_mol, N_ATOMS, aoff);

    k_transpose_planes<<<dim3(5 * D / 32, 8), dim3(32, 8)>>>(W_e,  we_hi,  we_lo,  5 * D);
    k_transpose_planes<<<dim3(4 * D / 32, 8), dim3(32, 8)>>>(W_v,  wv_hi,  wv_lo,  4 * D);
    k_transpose_planes<<<dim3(4 * D / 32, 8), dim3(32, 8)>>>(W_u,  wu_hi,  wu_lo,  4 * D);
    k_transpose_planes<<<dim3(D_IN / 32, 8),  dim3(32, 8)>>>(W_fv, wfv_hi, wfv_lo, D_IN);
    k_transpose_planes<<<dim3(D_IN / 32, 8),  dim3(32, 8)>>>(W_fu, wfu_hi, wfu_lo, D_IN);

    k_f2p<<<(int)((N_ATOMS * (size_t)D_IN / 2 + 255) / 256), 256>>>(atoms, at_hi, at_lo,
                                                                    N_ATOMS * D_IN / 2);
    k_init_he0<<<N_BONDS, 128>>>(bond_orders, W_fe, he0_hi, he0_lo, he_hi, he_lo);
    k_mol_mean<<<N_MOLS, 128>>>(atoms, aoff, mm_hi, mm_lo);
    cudaMemsetAsync(ebv_f, 0, SZ_V * sizeof(float), 0);

    // fork: E0 on side stream, everything else on main
    cudaEventRecord(evs[0], 0);
    cudaStreamWaitEvent(s1, evs[0], 0);
    {   // E0 = he0 @ We[256:512]
        Srcs s = {};
        s.Ahi[0] = he0_hi; s.Alo[0] = he0_lo; s.wblk[0] = 1;
        k_mma<<<dim3(2, N_BONDS / 128), 256, SMEM_BYTES, s1>>>(
            s, D, 3, 8, we_hi, we_lo, 5 * D, noadd, noscat, 0, 0, 0,
            E0, nullptr, nullptr, nullptr, nullptr, nullptr);
    }
    cudaEventRecord(evs[1], s1);

    {   // h_v0 = tanh(atoms @ W_fv); seed h_v
        Srcs s = {};
        s.Ahi[0] = at_hi; s.Alo[0] = at_lo; s.wblk[0] = 0;
        k_mma<<<dim3(2, N_ATOMS / 128), 256, SMEM_BYTES>>>(
            s, D_IN, 2, 4, wfv_hi, wfv_lo, D_IN, noadd, noscat, 1, 0, 0,
            nullptr, nullptr, hv0_hi, hv0_lo, hv_hi, hv_lo);
    }
    {   // h_u0 = tanh(mol_mean @ W_fu); seed h_u
        Srcs s = {};
        s.Ahi[0] = mm_hi; s.Alo[0] = mm_lo; s.wblk[0] = 0;
        k_mma<<<dim3(2, N_MOLS / 128), 256, SMEM_BYTES>>>(
            s, D_IN, 2, 4, wfu_hi, wfu_lo, D_IN, noadd, noscat, 1, 0, 0,
            nullptr, nullptr, hu0_hi, hu0_lo, hu_hi, hu_lo);
    }
    {   // V0t = hv0 @ Wv[256:512]
        Srcs s = {};
        s.Ahi[0] = hv0_hi; s.Alo[0] = hv0_lo; s.wblk[0] = 1;
        k_mma<<<dim3(2, N_ATOMS / 128), 256, SMEM_BYTES>>>(
            s, D, 3, 8, wv_hi, wv_lo, 4 * D, noadd, noscat, 0, 0, 0,
            V0t, nullptr, nullptr, nullptr, nullptr, nullptr);
    }
    {   // U0 = hu0 @ Wu[256:512]
        Srcs s = {};
        s.Ahi[0] = hu0_hi; s.Alo[0] = hu0_lo; s.wblk[0] = 1;
        k_mma<<<dim3(2, N_MOLS / 128), 256, SMEM_BYTES>>>(
            s, D, 3, 8, wu_hi, wu_lo, 4 * D, noadd, noscat, 0, 0, 0,
            U0, nullptr, nullptr, nullptr, nullptr, nullptr);
    }
    int ec = 0, vc = 0, uc = 0;
    {   // Ue(0), Uv(0)
        Srcs s = {};
        s.Ahi[0] = hu_hi; s.Alo[0] = hu_lo; s.wblk[0] = 4;
        k_mma<<<dim3(2, N_MOLS / 128), 256, SMEM_BYTES>>>(
            s, D, 3, 8, we_hi, we_lo, 5 * D, noadd, noscat, 0, 0, 0,
            Ue, nullptr, nullptr, nullptr, nullptr, nullptr);
        s.wblk[0] = 3;
        k_mma<<<dim3(2, N_MOLS / 128), 256, SMEM_BYTES>>>(
            s, D, 3, 8, wv_hi, wv_lo, 4 * D, noadd, noscat, 0, 0, 0,
            Uv, nullptr, nullptr, nullptr, nullptr, nullptr);
    }
    {   // Vs/Vd(0) merged
        Srcs s = {};
        s.Ahi[0] = hv_hi; s.Alo[0] = hv_lo; s.wblk[0] = 2;
        k_mma<<<dim3(2, 2 * N_ATOMS / 128), 256, SMEM_BYTES>>>(
            s, D, 3, 8, we_hi, we_lo, 5 * D, noadd, noscat, 0, N_ATOMS / 128, 3,
            Vs, Vd, nullptr, nullptr, nullptr, nullptr);
    }
    cudaStreamWaitEvent(0, evs[1], 0);   // E0 ready

    int evi = 2;
    for (int it = 0; it < 3; it++) {
        // edge update
        {
            Srcs s = {};
            s.Ahi[0] = he_hi + (size_t)ec * SZ_E;  s.Alo[0] = he_lo + (size_t)ec * SZ_E;
            s.wblk[0] = 0;
            Adds a = {};
            a.direct = E0;
            a.gat[0] = Ue; a.gidx[0] = bond_mol;
            a.gat[1] = Vs; a.gidx[1] = bond_src;
            a.gat[2] = Vd; a.gidx[2] = bond_dst;
            if (it == 2) {
                k_mma<<<dim3(2, N_BONDS / 128), 256, SMEM_BYTES>>>(
                    s, D, 3, 8, we_hi, we_lo, 5 * D, a, noscat, 1, 0, 0,
                    (float*)d_out, nullptr, nullptr, nullptr, nullptr, nullptr);
                break;
            }
            Scat sc = {ebv_f, bond_src, bond_dst};
            const int en = ec ^ 1;
            k_mma<<<dim3(2, N_BONDS / 128), 256, SMEM_BYTES>>>(
                s, D, 3, 8, we_hi, we_lo, 5 * D, a, sc, 1, 0, 0,
                nullptr, nullptr, he_hi + (size_t)en * SZ_E, he_lo + (size_t)en * SZ_E,
                nullptr, nullptr);
            ec = en;
        }

        // node update: srcs hv (planes) + ebv (fp32 direct); adds V0t + Uv[atom_mol]
        const int vn = vc ^ 1;
        {
            Srcs s = {};
            s.Ahi[0] = hv_hi + (size_t)vc * SZ_V;  s.Alo[0] = hv_lo + (size_t)vc * SZ_V;
            s.wblk[0] = 0;
            s.Ahi[1] = ebv_f;  s.wblk[1] = 2;  s.isf32[1] = 1;
            Adds a = {};
            a.direct = V0t;
            a.gat[0] = Uv; a.gidx[0] = atom_mol;
            k_mma<<<dim3(2, N_ATOMS / 128), 256, SMEM_BYTES>>>(
                s, D, 3, 16, wv_hi, wv_lo, 4 * D, a, noscat, 1, 0, 0,
                nullptr, nullptr, hv_hi + (size_t)vn * SZ_V, hv_lo + (size_t)vn * SZ_V,
                nullptr, nullptr);
            vc = vn;
        }

        // fork: Vs/Vd(it+1) on s1 (needs only new hv)
        cudaEventRecord(evs[evi], 0);
        cudaStreamWaitEvent(s1, evs[evi], 0);
        {
            Srcs s = {};
            s.Ahi[0] = hv_hi + (size_t)vc * SZ_V;  s.Alo[0] = hv_lo + (size_t)vc * SZ_V;
            s.wblk[0] = 2;
            k_mma<<<dim3(2, 2 * N_ATOMS / 128), 256, SMEM_BYTES, s1>>>(
                s, D, 3, 8, we_hi, we_lo, 5 * D, noadd, noscat, 0, N_ATOMS / 128, 3,
                Vs, Vd, nullptr, nullptr, nullptr, nullptr);
        }

        // main stream: clear ebv for next iter, segment sums, global update, Ue/Uv(it+1)
        cudaMemsetAsync(ebv_f, 0, SZ_V * sizeof(float), 0);
        k_segsum2<<<dim3(N_MOLS, 2), 256>>>(
            he_hi + (size_t)ec * SZ_E, he_lo + (size_t)ec * SZ_E, boff, ebar_hi, ebar_lo,
            hv_hi + (size_t)vc * SZ_V, hv_lo + (size_t)vc * SZ_V, aoff, vbar_hi, vbar_lo);
        const int un = uc ^ 1;
        {
            Srcs s = {};
            s.Ahi[0] = hu_hi + (size_t)uc * SZ_U;  s.Alo[0] = hu_lo + (size_t)uc * SZ_U;
            s.wblk[0] = 0;
            s.Ahi[1] = ebar_hi;  s.Alo[1] = ebar_lo;  s.wblk[1] = 2;
            s.Ahi[2] = vbar_hi;  s.Alo[2] = vbar_lo;  s.wblk[2] = 3;
            Adds a = {};
            a.direct = U0;
            k_mma<<<dim3(2, N_MOLS / 128), 256, SMEM_BYTES>>>(
                s, D, 3, 24, wu_hi, wu_lo, 4 * D, a, noscat, 1, 0, 0,
                nullptr, nullptr, hu_hi + (size_t)un * SZ_U, hu_lo + (size_t)un * SZ_U,
                nullptr, nullptr);
            uc = un;
        }
        {   // Ue(it+1); Uv(it+1) only if another node update follows
            Srcs s = {};
            s.Ahi[0] = hu_hi + (size_t)uc * SZ_U; s.Alo[0] = hu_lo + (size_t)uc * SZ_U;
            s.wblk[0] = 4;
            k_mma<<<dim3(2, N_MOLS / 128), 256, SMEM_BYTES>>>(
                s, D, 3, 8, we_hi, we_lo, 5 * D, noadd, noscat, 0, 0, 0,
                Ue, nullptr, nullptr, nullptr, nullptr, nullptr);
            if (it + 1 < 2) {
                s.wblk[0] = 3;
                k_mma<<<dim3(2, N_MOLS / 128), 256, SMEM_BYTES>>>(
                    s, D, 3, 8, wv_hi, wv_lo, 4 * D, noadd, noscat, 0, 0, 0,
                    Uv, nullptr, nullptr, nullptr, nullptr, nullptr);
            }
        }
        // join s1 before next edge
        cudaEventRecord(evs[evi + 1], s1);
        cudaStreamWaitEvent(0, evs[evi + 1], 0);
        evi += 2;
    }
}